// round 3
// baseline (speedup 1.0000x reference)
#include <cuda_runtime.h>
#include <cuda_bf16.h>
#include <math.h>
#include <stdint.h>

// Problem constants
#define BB 2
#define TT 2048
#define DD 1024
#define HH 16
#define DHH 64
#define FF 4096
#define MM (BB*TT)          // 4096 rows

// ---------------------------------------------------------------------------
// Scratch (allocation-free: __device__ globals)
// ---------------------------------------------------------------------------
__device__ float g_q[MM*DD];
__device__ float g_k[MM*DD];
__device__ float g_v[MM*DD];
__device__ float g_attn[MM*DD];
__device__ float g_y[MM*DD];
__device__ float g_x[MM*DD];
__device__ float g_h[MM*FF];
__device__ unsigned char g_mask[TT*TT];
__device__ int g_mask_mode;   // 0 = uint8 bytes, 1 = int32, 2 = float32

// ---------------------------------------------------------------------------
// Mask dtype detection: scan TT*TT/4 words (= minimum buffer size in bytes/4).
// uint8-packed bools give words outside {0,1,0x3F800000}; float32 gives
// {0, 0x3F800000}; int32 gives {0,1}.
// ---------------------------------------------------------------------------
__global__ __launch_bounds__(1024)
void mask_scan_kernel(const uint32_t* __restrict__ m)
{
    const int tid = threadIdx.x;
    int u8f = 0, f32f = 0;
    const int NW = (TT*TT) / 4;
    for (int i = tid; i < NW; i += 1024) {
        uint32_t w = m[i];
        if (w != 0u && w != 1u && w != 0x3F800000u) u8f = 1;
        if (w == 0x3F800000u) f32f = 1;
    }
    __shared__ int s_u8, s_f32;
    if (tid == 0) { s_u8 = 0; s_f32 = 0; }
    __syncthreads();
    if (u8f)  atomicOr(&s_u8, 1);
    if (f32f) atomicOr(&s_f32, 1);
    __syncthreads();
    if (tid == 0)
        g_mask_mode = s_u8 ? 0 : (s_f32 ? 2 : 1);
}

__global__ __launch_bounds__(256)
void mask_convert_kernel(const void* __restrict__ min)
{
    const int mode = g_mask_mode;
    int i = blockIdx.x * blockDim.x + threadIdx.x;   // word index into g_mask
    const int NW = (TT*TT) / 4;
    if (i >= NW) return;
    uint32_t out;
    if (mode == 0) {
        // already packed 0/1 bytes
        out = ((const uint32_t*)min)[i];
    } else if (mode == 1) {
        const int* p = (const int*)min;
        out  = (uint32_t)(p[4*i+0] != 0);
        out |= (uint32_t)(p[4*i+1] != 0) << 8;
        out |= (uint32_t)(p[4*i+2] != 0) << 16;
        out |= (uint32_t)(p[4*i+3] != 0) << 24;
    } else {
        const float* p = (const float*)min;
        out  = (uint32_t)(p[4*i+0] != 0.f);
        out |= (uint32_t)(p[4*i+1] != 0.f) << 8;
        out |= (uint32_t)(p[4*i+2] != 0.f) << 16;
        out |= (uint32_t)(p[4*i+3] != 0.f) << 24;
    }
    ((uint32_t*)g_mask)[i] = out;
}

// ---------------------------------------------------------------------------
// Generic NT GEMM: C[m,n] = sum_k A[m,k] * W[n,k] + bias[n]  (+ epilogue)
// EPI = 0: none, 1: relu, 2: res + alpha * (.)
// BM=BN=64, BK=32, 256 threads, 4x4 microtile
// ---------------------------------------------------------------------------
template<int EPI>
__global__ __launch_bounds__(256)
void gemm_nt(const float* __restrict__ A, const float* __restrict__ W,
             const float* __restrict__ bias, float* __restrict__ C,
             int M, int N, int K,
             const float* __restrict__ res, const float* __restrict__ alpha_p)
{
    __shared__ float As[32][65];   // [k][m]
    __shared__ float Bs[32][65];   // [k][n]

    const int bm = blockIdx.y * 64;
    const int bn = blockIdx.x * 64;
    const int tid = threadIdx.x;
    const int tx = tid & 15;       // 0..15 -> n
    const int ty = tid >> 4;       // 0..15 -> m

    float acc[4][4] = {};

    for (int k0 = 0; k0 < K; k0 += 32) {
        #pragma unroll
        for (int u = 0; u < 2; u++) {
            int idx = tid * 2 + u;          // 0..511
            int r   = idx >> 3;             // 0..63
            int c4  = (idx & 7) << 2;       // 0,4,...,28
            float4 a = *(const float4*)&A[(size_t)(bm + r) * K + k0 + c4];
            As[c4+0][r] = a.x; As[c4+1][r] = a.y; As[c4+2][r] = a.z; As[c4+3][r] = a.w;
            float4 b = *(const float4*)&W[(size_t)(bn + r) * K + k0 + c4];
            Bs[c4+0][r] = b.x; Bs[c4+1][r] = b.y; Bs[c4+2][r] = b.z; Bs[c4+3][r] = b.w;
        }
        __syncthreads();

        #pragma unroll
        for (int k = 0; k < 32; k++) {
            float ra[4], rb[4];
            #pragma unroll
            for (int i = 0; i < 4; i++) ra[i] = As[k][ty*4 + i];
            #pragma unroll
            for (int j = 0; j < 4; j++) rb[j] = Bs[k][tx*4 + j];
            #pragma unroll
            for (int i = 0; i < 4; i++)
                #pragma unroll
                for (int j = 0; j < 4; j++)
                    acc[i][j] = fmaf(ra[i], rb[j], acc[i][j]);
        }
        __syncthreads();
    }

    float alpha = 0.f;
    if (EPI == 2) alpha = *alpha_p;

    #pragma unroll
    for (int i = 0; i < 4; i++) {
        int m = bm + ty*4 + i;
        #pragma unroll
        for (int j = 0; j < 4; j++) {
            int n = bn + tx*4 + j;
            float v = acc[i][j] + bias[n];
            if (EPI == 1) v = fmaxf(v, 0.f);
            if (EPI == 2) v = res[(size_t)m * N + n] + alpha * v;
            C[(size_t)m * N + n] = v;
        }
    }
}

// ---------------------------------------------------------------------------
// Flash attention (fp32). One block = one (b,h) + 64 query rows.
// Q/K/V layout: [B*T, D] where head h occupies columns [h*64, h*64+64).
// mask: canonical uint8 [T,T], nonzero = masked. Fully-masked rows -> 0 out.
// ---------------------------------------------------------------------------
#define FLASH_SMEM (4*64*65*4 + 64*64)

__global__ __launch_bounds__(256)
void flash_attn(const float* __restrict__ Q, const float* __restrict__ Kb,
                const float* __restrict__ Vb, const unsigned char* __restrict__ mask,
                float* __restrict__ O)
{
    extern __shared__ unsigned char sm_raw[];
    float* Qst = (float*)sm_raw;            // [d][r]   64x65
    float* Kst = Qst + 64*65;               // [d][s]   64x65
    float* Vs  = Kst + 64*65;               // [s][d]   64x65
    float* Ps  = Vs  + 64*65;               // [s][r]   64x65
    unsigned char* Ms = (unsigned char*)(Ps + 64*65);  // [r][s] 64x64

    const int q0 = blockIdx.x * 64;
    const int h  = blockIdx.y;
    const int b  = blockIdx.z;
    const int tid = threadIdx.x;
    const int tx = tid & 15;
    const int ty = tid >> 4;

    const size_t base = ((size_t)b * TT) * DD + h * DHH;
    const float scale = 0.125f;  // 1/sqrt(64)

    // Load Q tile -> Qst[d][r]
    #pragma unroll
    for (int u = 0; u < 4; u++) {
        int idx = tid + u * 256;            // 0..1023 float4 slots
        int r = idx >> 4;
        int d0 = (idx & 15) << 2;
        float4 q = *(const float4*)&Q[base + (size_t)(q0 + r) * DD + d0];
        Qst[(d0+0)*65 + r] = q.x; Qst[(d0+1)*65 + r] = q.y;
        Qst[(d0+2)*65 + r] = q.z; Qst[(d0+3)*65 + r] = q.w;
    }

    float m_i[4], l_i[4], acc[4][4];
    #pragma unroll
    for (int i = 0; i < 4; i++) { m_i[i] = -1e30f; l_i[i] = 0.f; }
    #pragma unroll
    for (int i = 0; i < 4; i++)
        #pragma unroll
        for (int j = 0; j < 4; j++) acc[i][j] = 0.f;

    for (int s0 = 0; s0 < TT; s0 += 64) {
        __syncthreads();  // protect Kst/Vs/Ms/Ps from previous iteration readers

        // Load K tile -> Kst[d][s], V tile -> Vs[s][d]
        #pragma unroll
        for (int u = 0; u < 4; u++) {
            int idx = tid + u * 256;
            int s = idx >> 4;
            int d0 = (idx & 15) << 2;
            float4 kv = *(const float4*)&Kb[base + (size_t)(s0 + s) * DD + d0];
            Kst[(d0+0)*65 + s] = kv.x; Kst[(d0+1)*65 + s] = kv.y;
            Kst[(d0+2)*65 + s] = kv.z; Kst[(d0+3)*65 + s] = kv.w;
            float4 vv = *(const float4*)&Vb[base + (size_t)(s0 + s) * DD + d0];
            Vs[s*65 + d0+0] = vv.x; Vs[s*65 + d0+1] = vv.y;
            Vs[s*65 + d0+2] = vv.z; Vs[s*65 + d0+3] = vv.w;
        }
        // Load mask tile (64x64 bytes) via int4
        {
            int mr = tid >> 2;
            int mc = (tid & 3) << 4;
            int4 mv = *(const int4*)&mask[(size_t)(q0 + mr) * TT + s0 + mc];
            *(int4*)&Ms[mr*64 + mc] = mv;
        }
        __syncthreads();

        // S = Q K^T
        float sacc[4][4] = {};
        #pragma unroll
        for (int d = 0; d < 64; d++) {
            float rq[4], rk[4];
            #pragma unroll
            for (int i = 0; i < 4; i++) rq[i] = Qst[d*65 + ty*4 + i];
            #pragma unroll
            for (int j = 0; j < 4; j++) rk[j] = Kst[d*65 + tx*4 + j];
            #pragma unroll
            for (int i = 0; i < 4; i++)
                #pragma unroll
                for (int j = 0; j < 4; j++)
                    sacc[i][j] = fmaf(rq[i], rk[j], sacc[i][j]);
        }

        // Online softmax update
        #pragma unroll
        for (int i = 0; i < 4; i++) {
            int r = ty*4 + i;
            bool msk[4];
            float sv[4];
            float tm = -1e30f;
            #pragma unroll
            for (int j = 0; j < 4; j++) {
                msk[j] = Ms[r*64 + tx*4 + j] != 0;
                sv[j] = msk[j] ? -1e30f : sacc[i][j] * scale;
                tm = fmaxf(tm, sv[j]);
            }
            #pragma unroll
            for (int off = 8; off >= 1; off >>= 1)
                tm = fmaxf(tm, __shfl_xor_sync(0xffffffffu, tm, off));

            float mnew = fmaxf(m_i[i], tm);
            float af = __expf(m_i[i] - mnew);
            float rs = 0.f;
            #pragma unroll
            for (int j = 0; j < 4; j++) {
                float p = msk[j] ? 0.f : __expf(sv[j] - mnew);
                Ps[(tx*4 + j)*65 + r] = p;
                rs += p;
            }
            #pragma unroll
            for (int off = 8; off >= 1; off >>= 1)
                rs += __shfl_xor_sync(0xffffffffu, rs, off);

            l_i[i] = af * l_i[i] + rs;
            m_i[i] = mnew;
            #pragma unroll
            for (int j = 0; j < 4; j++) acc[i][j] *= af;
        }
        __syncthreads();

        // acc += P V
        #pragma unroll
        for (int s = 0; s < 64; s++) {
            float rp[4], rv[4];
            #pragma unroll
            for (int i = 0; i < 4; i++) rp[i] = Ps[s*65 + ty*4 + i];
            #pragma unroll
            for (int j = 0; j < 4; j++) rv[j] = Vs[s*65 + tx*4 + j];
            #pragma unroll
            for (int i = 0; i < 4; i++)
                #pragma unroll
                for (int j = 0; j < 4; j++)
                    acc[i][j] = fmaf(rp[i], rv[j], acc[i][j]);
        }
    }

    #pragma unroll
    for (int i = 0; i < 4; i++) {
        float inv = (l_i[i] > 0.f) ? 1.f / l_i[i] : 0.f;
        int r = q0 + ty*4 + i;
        #pragma unroll
        for (int j = 0; j < 4; j++)
            O[base + (size_t)r * DD + tx*4 + j] = acc[i][j] * inv;
    }
}

// ---------------------------------------------------------------------------
// Row LayerNorm: block per row of 1024, 256 threads (float4 each)
// ---------------------------------------------------------------------------
__global__ __launch_bounds__(256)
void ln_kernel(const float* __restrict__ Y, const float* __restrict__ sc,
               const float* __restrict__ bi, float* __restrict__ X)
{
    const int row = blockIdx.x;
    const int tid = threadIdx.x;
    const float4 v = ((const float4*)(Y + (size_t)row * DD))[tid];

    float s  = v.x + v.y + v.z + v.w;
    float ss = v.x*v.x + v.y*v.y + v.z*v.z + v.w*v.w;
    #pragma unroll
    for (int off = 16; off >= 1; off >>= 1) {
        s  += __shfl_xor_sync(0xffffffffu, s,  off);
        ss += __shfl_xor_sync(0xffffffffu, ss, off);
    }

    __shared__ float ws[8], wss[8];
    __shared__ float mean_sh, rstd_sh;
    if ((tid & 31) == 0) { ws[tid >> 5] = s; wss[tid >> 5] = ss; }
    __syncthreads();
    if (tid == 0) {
        float S = 0.f, SS = 0.f;
        #pragma unroll
        for (int k = 0; k < 8; k++) { S += ws[k]; SS += wss[k]; }
        float mu = S / (float)DD;
        float var = SS / (float)DD - mu * mu;
        mean_sh = mu;
        rstd_sh = rsqrtf(var + 1e-5f);
    }
    __syncthreads();
    const float mu = mean_sh, rs = rstd_sh;

    const float4 sc4 = ((const float4*)sc)[tid];
    const float4 b4  = ((const float4*)bi)[tid];
    float4 o;
    o.x = (v.x - mu) * rs * sc4.x + b4.x;
    o.y = (v.y - mu) * rs * sc4.y + b4.y;
    o.z = (v.z - mu) * rs * sc4.z + b4.z;
    o.w = (v.w - mu) * rs * sc4.w + b4.w;
    ((float4*)(X + (size_t)row * DD))[tid] = o;
}

// ---------------------------------------------------------------------------
// Launch
// ---------------------------------------------------------------------------
extern "C" void kernel_launch(void* const* d_in, const int* in_sizes, int n_in,
                              void* d_out, int out_size)
{
    const float* src  = (const float*)d_in[0];
    const void*  mask_raw = d_in[1];
    const float* q_w = (const float*)d_in[2];
    const float* q_b = (const float*)d_in[3];
    const float* k_w = (const float*)d_in[4];
    const float* k_b = (const float*)d_in[5];
    const float* v_w = (const float*)d_in[6];
    const float* v_b = (const float*)d_in[7];
    const float* o_w = (const float*)d_in[8];
    const float* o_b = (const float*)d_in[9];
    const float* l1_w = (const float*)d_in[10];
    const float* l1_b = (const float*)d_in[11];
    const float* l2_w = (const float*)d_in[12];
    const float* l2_b = (const float*)d_in[13];
    const float* n1_s = (const float*)d_in[14];
    const float* n1_b = (const float*)d_in[15];
    const float* n2_s = (const float*)d_in[16];
    const float* n2_b = (const float*)d_in[17];
    const float* alpha_attn = (const float*)d_in[18];
    const float* alpha_ff   = (const float*)d_in[19];

    float *q, *k, *v, *attn, *y, *x, *hbuf;
    unsigned char* maskc;
    cudaGetSymbolAddress((void**)&q,    g_q);
    cudaGetSymbolAddress((void**)&k,    g_k);
    cudaGetSymbolAddress((void**)&v,    g_v);
    cudaGetSymbolAddress((void**)&attn, g_attn);
    cudaGetSymbolAddress((void**)&y,    g_y);
    cudaGetSymbolAddress((void**)&x,    g_x);
    cudaGetSymbolAddress((void**)&hbuf, g_h);
    cudaGetSymbolAddress((void**)&maskc, g_mask);

    dim3 blk(256);
    dim3 grid_d(DD/64, MM/64);     // (16, 64)
    dim3 grid_f(FF/64, MM/64);     // (64, 64)

    // Canonicalize mask to uint8 (handles bool/int32/float32 storage)
    mask_scan_kernel<<<1, 1024>>>((const uint32_t*)mask_raw);
    mask_convert_kernel<<<(TT*TT/4 + 255)/256, 256>>>(mask_raw);

    // QKV projections
    gemm_nt<0><<<grid_d, blk>>>(src, q_w, q_b, q, MM, DD, DD, nullptr, nullptr);
    gemm_nt<0><<<grid_d, blk>>>(src, k_w, k_b, k, MM, DD, DD, nullptr, nullptr);
    gemm_nt<0><<<grid_d, blk>>>(src, v_w, v_b, v, MM, DD, DD, nullptr, nullptr);

    // Flash attention
    cudaFuncSetAttribute(flash_attn, cudaFuncAttributeMaxDynamicSharedMemorySize, FLASH_SMEM);
    flash_attn<<<dim3(TT/64, HH, BB), blk, FLASH_SMEM>>>(q, k, v, maskc, attn);

    // O projection + residual
    gemm_nt<2><<<grid_d, blk>>>(attn, o_w, o_b, y, MM, DD, DD, src, alpha_attn);
    ln_kernel<<<MM, 256>>>(y, n1_s, n1_b, x);

    // FFN
    gemm_nt<1><<<grid_f, blk>>>(x, l1_w, l1_b, hbuf, MM, FF, DD, nullptr, nullptr);
    gemm_nt<2><<<grid_d, blk>>>(hbuf, l2_w, l2_b, y, MM, DD, FF, x, alpha_ff);
    ln_kernel<<<MM, 256>>>(y, n2_s, n2_b, (float*)d_out);
}

// round 4
// speedup vs baseline: 1.2920x; 1.2920x over previous
#include <cuda_runtime.h>
#include <cuda_bf16.h>
#include <math.h>
#include <stdint.h>

// Problem constants
#define BB 2
#define TT 2048
#define DD 1024
#define HH 16
#define DHH 64
#define FF 4096
#define MM (BB*TT)          // 4096 rows

typedef unsigned long long ull;

// ---------------------------------------------------------------------------
// Packed fp32x2 helpers (Blackwell FFMA2) — bitwise-identical to 2x scalar fp32
// ---------------------------------------------------------------------------
__device__ __forceinline__ ull fdup(float x) {
    ull r;
    asm("mov.b64 %0, {%1, %1};" : "=l"(r) : "r"(__float_as_uint(x)));
    return r;
}
__device__ __forceinline__ void ffma2(ull& d, ull a, ull b) {
    asm("fma.rn.f32x2 %0, %1, %2, %0;" : "+l"(d) : "l"(a), "l"(b));
}
__device__ __forceinline__ void fmul2(ull& d, ull a) {
    asm("mul.rn.f32x2 %0, %0, %1;" : "+l"(d) : "l"(a));
}
__device__ __forceinline__ float2 unpk(ull v) {
    uint32_t lo, hi;
    asm("mov.b64 {%0, %1}, %2;" : "=r"(lo), "=r"(hi) : "l"(v));
    return make_float2(__uint_as_float(lo), __uint_as_float(hi));
}

// ---------------------------------------------------------------------------
// Scratch (allocation-free: __device__ globals)
// ---------------------------------------------------------------------------
__device__ float g_q[MM*DD];
__device__ float g_k[MM*DD];
__device__ float g_v[MM*DD];
__device__ float g_attn[MM*DD];
__device__ float g_y[MM*DD];
__device__ float g_x[MM*DD];
__device__ float g_h[MM*FF];
__device__ unsigned char g_mask[TT*TT];
__device__ int g_mask_mode;   // 0 = uint8 bytes, 1 = int32, 2 = float32

// ---------------------------------------------------------------------------
// Mask dtype detection + canonicalization to uint8
// ---------------------------------------------------------------------------
__global__ __launch_bounds__(1024)
void mask_scan_kernel(const uint32_t* __restrict__ m)
{
    const int tid = threadIdx.x;
    int u8f = 0, f32f = 0;
    const int NW = (TT*TT) / 4;
    for (int i = tid; i < NW; i += 1024) {
        uint32_t w = m[i];
        if (w != 0u && w != 1u && w != 0x3F800000u) u8f = 1;
        if (w == 0x3F800000u) f32f = 1;
    }
    __shared__ int s_u8, s_f32;
    if (tid == 0) { s_u8 = 0; s_f32 = 0; }
    __syncthreads();
    if (u8f)  atomicOr(&s_u8, 1);
    if (f32f) atomicOr(&s_f32, 1);
    __syncthreads();
    if (tid == 0)
        g_mask_mode = s_u8 ? 0 : (s_f32 ? 2 : 1);
}

__global__ __launch_bounds__(256)
void mask_convert_kernel(const void* __restrict__ min)
{
    const int mode = g_mask_mode;
    int i = blockIdx.x * blockDim.x + threadIdx.x;
    const int NW = (TT*TT) / 4;
    if (i >= NW) return;
    uint32_t out;
    if (mode == 0) {
        out = ((const uint32_t*)min)[i];
    } else if (mode == 1) {
        const int* p = (const int*)min;
        out  = (uint32_t)(p[4*i+0] != 0);
        out |= (uint32_t)(p[4*i+1] != 0) << 8;
        out |= (uint32_t)(p[4*i+2] != 0) << 16;
        out |= (uint32_t)(p[4*i+3] != 0) << 24;
    } else {
        const float* p = (const float*)min;
        out  = (uint32_t)(p[4*i+0] != 0.f);
        out |= (uint32_t)(p[4*i+1] != 0.f) << 8;
        out |= (uint32_t)(p[4*i+2] != 0.f) << 16;
        out |= (uint32_t)(p[4*i+3] != 0.f) << 24;
    }
    ((uint32_t*)g_mask)[i] = out;
}

// ---------------------------------------------------------------------------
// NT GEMM: C[m,n] = sum_k A[m,k] * W[n,k] + bias[n]  (+ epilogue)
// EPI = 0: none, 1: relu, 2: res + alpha * (.)
// 128x128x16 tiles, 256 threads, 8x8 microtile, FFMA2 packed math,
// LDG prefetch of next k-tile overlapped with compute.
// ---------------------------------------------------------------------------
#define BMg 128
#define BNg 128
#define BKg 16

template<int EPI>
__global__ __launch_bounds__(256, 2)
void gemm_nt(const float* __restrict__ A, const float* __restrict__ W,
             const float* __restrict__ bias, float* __restrict__ C,
             int M, int N, int K,
             const float* __restrict__ res, const float* __restrict__ alpha_p)
{
    __shared__ float As[BKg][132];   // [k][m], 132*4B row stride (16B-aligned)
    __shared__ float Bs[BKg][132];   // [k][n]

    const int bm = blockIdx.y * BMg;
    const int bn = blockIdx.x * BNg;
    const int tid = threadIdx.x;
    const int tx = tid & 15;        // n / 8
    const int ty = tid >> 4;        // m / 8

    // Staging mapping: thread loads row r, k-cols c8..c8+7 (two float4)
    const int r  = tid >> 1;        // 0..127
    const int c8 = (tid & 1) * 8;   // 0 or 8

    const float* Arow = A + (size_t)(bm + r) * K + c8;
    const float* Wrow = W + (size_t)(bn + r) * K + c8;

    ull acc2[8][4];
    #pragma unroll
    for (int i = 0; i < 8; i++)
        #pragma unroll
        for (int j = 0; j < 4; j++) acc2[i][j] = 0ull;

    // Prologue: load k-tile 0
    float4 pa0 = *(const float4*)(Arow + 0);
    float4 pa1 = *(const float4*)(Arow + 4);
    float4 pb0 = *(const float4*)(Wrow + 0);
    float4 pb1 = *(const float4*)(Wrow + 4);

    const int KT = K / BKg;
    for (int kt = 0; kt < KT; kt++) {
        // store staged regs -> smem (transposed)
        #pragma unroll
        for (int j = 0; j < 4; j++) {
            As[c8 + j][r]     = ((const float*)&pa0)[j];
            As[c8 + 4 + j][r] = ((const float*)&pa1)[j];
            Bs[c8 + j][r]     = ((const float*)&pb0)[j];
            Bs[c8 + 4 + j][r] = ((const float*)&pb1)[j];
        }
        __syncthreads();

        // prefetch next k-tile
        if (kt + 1 < KT) {
            const float* An = Arow + (size_t)(kt + 1) * BKg;
            const float* Wn = Wrow + (size_t)(kt + 1) * BKg;
            pa0 = *(const float4*)(An + 0);
            pa1 = *(const float4*)(An + 4);
            pb0 = *(const float4*)(Wn + 0);
            pb1 = *(const float4*)(Wn + 4);
        }

        #pragma unroll
        for (int k = 0; k < BKg; k++) {
            ulonglong2 b01 = *(const ulonglong2*)&Bs[k][tx*8];
            ulonglong2 b23 = *(const ulonglong2*)&Bs[k][tx*8 + 4];
            float4 a0 = *(const float4*)&As[k][ty*8];
            float4 a1 = *(const float4*)&As[k][ty*8 + 4];
            ull ad[8];
            ad[0] = fdup(a0.x); ad[1] = fdup(a0.y); ad[2] = fdup(a0.z); ad[3] = fdup(a0.w);
            ad[4] = fdup(a1.x); ad[5] = fdup(a1.y); ad[6] = fdup(a1.z); ad[7] = fdup(a1.w);
            #pragma unroll
            for (int i = 0; i < 8; i++) {
                ffma2(acc2[i][0], ad[i], b01.x);
                ffma2(acc2[i][1], ad[i], b01.y);
                ffma2(acc2[i][2], ad[i], b23.x);
                ffma2(acc2[i][3], ad[i], b23.y);
            }
        }
        __syncthreads();
    }

    float alpha = 0.f;
    if (EPI == 2) alpha = *alpha_p;

    const float4 bias0 = *(const float4*)&bias[bn + tx*8];
    const float4 bias1 = *(const float4*)&bias[bn + tx*8 + 4];

    #pragma unroll
    for (int i = 0; i < 8; i++) {
        const int m = bm + ty*8 + i;
        #pragma unroll
        for (int q = 0; q < 2; q++) {
            const int n = bn + tx*8 + q*4;
            float2 p0 = unpk(acc2[i][2*q]);
            float2 p1 = unpk(acc2[i][2*q + 1]);
            const float4 b4 = q ? bias1 : bias0;
            float4 o;
            o.x = p0.x + b4.x; o.y = p0.y + b4.y;
            o.z = p1.x + b4.z; o.w = p1.y + b4.w;
            if (EPI == 1) {
                o.x = fmaxf(o.x, 0.f); o.y = fmaxf(o.y, 0.f);
                o.z = fmaxf(o.z, 0.f); o.w = fmaxf(o.w, 0.f);
            }
            if (EPI == 2) {
                float4 r4 = *(const float4*)&res[(size_t)m * N + n];
                o.x = r4.x + alpha * o.x; o.y = r4.y + alpha * o.y;
                o.z = r4.z + alpha * o.z; o.w = r4.w + alpha * o.w;
            }
            *(float4*)&C[(size_t)m * N + n] = o;
        }
    }
}

// ---------------------------------------------------------------------------
// Flash attention (fp32, FFMA2 inner loops). One block = (b,h) + 64 q rows.
// mask: canonical uint8 [T,T], nonzero = masked. Fully-masked rows -> 0 out.
// Smem stride 68 floats (16B-aligned rows for LDS.128).
// ---------------------------------------------------------------------------
#define FAS 68
#define FLASH_SMEM (4*64*FAS*4 + 64*64)

__global__ __launch_bounds__(256)
void flash_attn(const float* __restrict__ Q, const float* __restrict__ Kb,
                const float* __restrict__ Vb, const unsigned char* __restrict__ mask,
                float* __restrict__ O)
{
    extern __shared__ unsigned char sm_raw[];
    float* Qst = (float*)sm_raw;            // [d][r]   64xFAS
    float* Kst = Qst + 64*FAS;              // [d][s]   64xFAS
    float* Vs  = Kst + 64*FAS;              // [s][d]   64xFAS
    float* Ps  = Vs  + 64*FAS;              // [s][r]   64xFAS
    unsigned char* Ms = (unsigned char*)(Ps + 64*FAS);  // [r][s] 64x64

    const int q0 = blockIdx.x * 64;
    const int h  = blockIdx.y;
    const int b  = blockIdx.z;
    const int tid = threadIdx.x;
    const int tx = tid & 15;
    const int ty = tid >> 4;

    const size_t base = ((size_t)b * TT) * DD + h * DHH;
    const float scale = 0.125f;  // 1/sqrt(64)

    // Load Q tile -> Qst[d][r]
    #pragma unroll
    for (int u = 0; u < 4; u++) {
        int idx = tid + u * 256;
        int r = idx >> 4;
        int d0 = (idx & 15) << 2;
        float4 q = *(const float4*)&Q[base + (size_t)(q0 + r) * DD + d0];
        Qst[(d0+0)*FAS + r] = q.x; Qst[(d0+1)*FAS + r] = q.y;
        Qst[(d0+2)*FAS + r] = q.z; Qst[(d0+3)*FAS + r] = q.w;
    }

    float m_i[4], l_i[4];
    ull acc2[4][2];
    #pragma unroll
    for (int i = 0; i < 4; i++) {
        m_i[i] = -1e30f; l_i[i] = 0.f;
        acc2[i][0] = 0ull; acc2[i][1] = 0ull;
    }

    for (int s0 = 0; s0 < TT; s0 += 64) {
        __syncthreads();

        // Load K tile -> Kst[d][s], V tile -> Vs[s][d]
        #pragma unroll
        for (int u = 0; u < 4; u++) {
            int idx = tid + u * 256;
            int s = idx >> 4;
            int d0 = (idx & 15) << 2;
            float4 kv = *(const float4*)&Kb[base + (size_t)(s0 + s) * DD + d0];
            Kst[(d0+0)*FAS + s] = kv.x; Kst[(d0+1)*FAS + s] = kv.y;
            Kst[(d0+2)*FAS + s] = kv.z; Kst[(d0+3)*FAS + s] = kv.w;
            float4 vv = *(const float4*)&Vb[base + (size_t)(s0 + s) * DD + d0];
            Vs[s*FAS + d0+0] = vv.x; Vs[s*FAS + d0+1] = vv.y;
            Vs[s*FAS + d0+2] = vv.z; Vs[s*FAS + d0+3] = vv.w;
        }
        // Load mask tile (64x64 bytes)
        {
            int mr = tid >> 2;
            int mc = (tid & 3) << 4;
            int4 mv = *(const int4*)&mask[(size_t)(q0 + mr) * TT + s0 + mc];
            *(int4*)&Ms[mr*64 + mc] = mv;
        }
        __syncthreads();

        // S = Q K^T (packed pairs along s)
        ull sacc2[4][2];
        #pragma unroll
        for (int i = 0; i < 4; i++) { sacc2[i][0] = 0ull; sacc2[i][1] = 0ull; }
        #pragma unroll
        for (int d = 0; d < 64; d++) {
            float4 q4 = *(const float4*)&Qst[d*FAS + ty*4];
            ulonglong2 k2 = *(const ulonglong2*)&Kst[d*FAS + tx*4];
            ull qd[4];
            qd[0] = fdup(q4.x); qd[1] = fdup(q4.y); qd[2] = fdup(q4.z); qd[3] = fdup(q4.w);
            #pragma unroll
            for (int i = 0; i < 4; i++) {
                ffma2(sacc2[i][0], qd[i], k2.x);
                ffma2(sacc2[i][1], qd[i], k2.y);
            }
        }

        // Online softmax update
        #pragma unroll
        for (int i = 0; i < 4; i++) {
            int r = ty*4 + i;
            float2 s01 = unpk(sacc2[i][0]);
            float2 s23 = unpk(sacc2[i][1]);
            float sac[4] = { s01.x, s01.y, s23.x, s23.y };
            bool msk[4];
            float sv[4];
            float tm = -1e30f;
            #pragma unroll
            for (int j = 0; j < 4; j++) {
                msk[j] = Ms[r*64 + tx*4 + j] != 0;
                sv[j] = msk[j] ? -1e30f : sac[j] * scale;
                tm = fmaxf(tm, sv[j]);
            }
            #pragma unroll
            for (int off = 8; off >= 1; off >>= 1)
                tm = fmaxf(tm, __shfl_xor_sync(0xffffffffu, tm, off));

            float mnew = fmaxf(m_i[i], tm);
            float af = __expf(m_i[i] - mnew);
            float rs = 0.f;
            #pragma unroll
            for (int j = 0; j < 4; j++) {
                float p = msk[j] ? 0.f : __expf(sv[j] - mnew);
                Ps[(tx*4 + j)*FAS + r] = p;
                rs += p;
            }
            #pragma unroll
            for (int off = 8; off >= 1; off >>= 1)
                rs += __shfl_xor_sync(0xffffffffu, rs, off);

            l_i[i] = af * l_i[i] + rs;
            m_i[i] = mnew;
            ull afd = fdup(af);
            fmul2(acc2[i][0], afd);
            fmul2(acc2[i][1], afd);
        }
        __syncthreads();

        // acc += P V (packed pairs along d)
        #pragma unroll
        for (int s = 0; s < 64; s++) {
            float4 p4 = *(const float4*)&Ps[s*FAS + ty*4];
            ulonglong2 v2 = *(const ulonglong2*)&Vs[s*FAS + tx*4];
            ull pd[4];
            pd[0] = fdup(p4.x); pd[1] = fdup(p4.y); pd[2] = fdup(p4.z); pd[3] = fdup(p4.w);
            #pragma unroll
            for (int i = 0; i < 4; i++) {
                ffma2(acc2[i][0], pd[i], v2.x);
                ffma2(acc2[i][1], pd[i], v2.y);
            }
        }
    }

    #pragma unroll
    for (int i = 0; i < 4; i++) {
        float inv = (l_i[i] > 0.f) ? 1.f / l_i[i] : 0.f;
        int r = q0 + ty*4 + i;
        float2 o0 = unpk(acc2[i][0]);
        float2 o1 = unpk(acc2[i][1]);
        float4 o = make_float4(o0.x * inv, o0.y * inv, o1.x * inv, o1.y * inv);
        *(float4*)&O[base + (size_t)r * DD + tx*4] = o;
    }
}

// ---------------------------------------------------------------------------
// Row LayerNorm: block per row of 1024, 256 threads (float4 each)
// ---------------------------------------------------------------------------
__global__ __launch_bounds__(256)
void ln_kernel(const float* __restrict__ Y, const float* __restrict__ sc,
               const float* __restrict__ bi, float* __restrict__ X)
{
    const int row = blockIdx.x;
    const int tid = threadIdx.x;
    const float4 v = ((const float4*)(Y + (size_t)row * DD))[tid];

    float s  = v.x + v.y + v.z + v.w;
    float ss = v.x*v.x + v.y*v.y + v.z*v.z + v.w*v.w;
    #pragma unroll
    for (int off = 16; off >= 1; off >>= 1) {
        s  += __shfl_xor_sync(0xffffffffu, s,  off);
        ss += __shfl_xor_sync(0xffffffffu, ss, off);
    }

    __shared__ float ws[8], wss[8];
    __shared__ float mean_sh, rstd_sh;
    if ((tid & 31) == 0) { ws[tid >> 5] = s; wss[tid >> 5] = ss; }
    __syncthreads();
    if (tid == 0) {
        float S = 0.f, SS = 0.f;
        #pragma unroll
        for (int k = 0; k < 8; k++) { S += ws[k]; SS += wss[k]; }
        float mu = S / (float)DD;
        float var = SS / (float)DD - mu * mu;
        mean_sh = mu;
        rstd_sh = rsqrtf(var + 1e-5f);
    }
    __syncthreads();
    const float mu = mean_sh, rs = rstd_sh;

    const float4 sc4 = ((const float4*)sc)[tid];
    const float4 b4  = ((const float4*)bi)[tid];
    float4 o;
    o.x = (v.x - mu) * rs * sc4.x + b4.x;
    o.y = (v.y - mu) * rs * sc4.y + b4.y;
    o.z = (v.z - mu) * rs * sc4.z + b4.z;
    o.w = (v.w - mu) * rs * sc4.w + b4.w;
    ((float4*)(X + (size_t)row * DD))[tid] = o;
}

// ---------------------------------------------------------------------------
// Launch
// ---------------------------------------------------------------------------
extern "C" void kernel_launch(void* const* d_in, const int* in_sizes, int n_in,
                              void* d_out, int out_size)
{
    const float* src  = (const float*)d_in[0];
    const void*  mask_raw = d_in[1];
    const float* q_w = (const float*)d_in[2];
    const float* q_b = (const float*)d_in[3];
    const float* k_w = (const float*)d_in[4];
    const float* k_b = (const float*)d_in[5];
    const float* v_w = (const float*)d_in[6];
    const float* v_b = (const float*)d_in[7];
    const float* o_w = (const float*)d_in[8];
    const float* o_b = (const float*)d_in[9];
    const float* l1_w = (const float*)d_in[10];
    const float* l1_b = (const float*)d_in[11];
    const float* l2_w = (const float*)d_in[12];
    const float* l2_b = (const float*)d_in[13];
    const float* n1_s = (const float*)d_in[14];
    const float* n1_b = (const float*)d_in[15];
    const float* n2_s = (const float*)d_in[16];
    const float* n2_b = (const float*)d_in[17];
    const float* alpha_attn = (const float*)d_in[18];
    const float* alpha_ff   = (const float*)d_in[19];

    float *q, *k, *v, *attn, *y, *x, *hbuf;
    unsigned char* maskc;
    cudaGetSymbolAddress((void**)&q,    g_q);
    cudaGetSymbolAddress((void**)&k,    g_k);
    cudaGetSymbolAddress((void**)&v,    g_v);
    cudaGetSymbolAddress((void**)&attn, g_attn);
    cudaGetSymbolAddress((void**)&y,    g_y);
    cudaGetSymbolAddress((void**)&x,    g_x);
    cudaGetSymbolAddress((void**)&hbuf, g_h);
    cudaGetSymbolAddress((void**)&maskc, g_mask);

    dim3 blk(256);
    dim3 grid_d(DD/BNg, MM/BMg);     // (8, 32)
    dim3 grid_f(FF/BNg, MM/BMg);     // (32, 32)

    // Canonicalize mask to uint8
    mask_scan_kernel<<<1, 1024>>>((const uint32_t*)mask_raw);
    mask_convert_kernel<<<(TT*TT/4 + 255)/256, 256>>>(mask_raw);

    // QKV projections
    gemm_nt<0><<<grid_d, blk>>>(src, q_w, q_b, q, MM, DD, DD, nullptr, nullptr);
    gemm_nt<0><<<grid_d, blk>>>(src, k_w, k_b, k, MM, DD, DD, nullptr, nullptr);
    gemm_nt<0><<<grid_d, blk>>>(src, v_w, v_b, v, MM, DD, DD, nullptr, nullptr);

    // Flash attention
    cudaFuncSetAttribute(flash_attn, cudaFuncAttributeMaxDynamicSharedMemorySize, FLASH_SMEM);
    flash_attn<<<dim3(TT/64, HH, BB), blk, FLASH_SMEM>>>(q, k, v, maskc, attn);

    // O projection + residual
    gemm_nt<2><<<grid_d, blk>>>(attn, o_w, o_b, y, MM, DD, DD, src, alpha_attn);
    ln_kernel<<<MM, 256>>>(y, n1_s, n1_b, x);

    // FFN
    gemm_nt<1><<<grid_f, blk>>>(x, l1_w, l1_b, hbuf, MM, FF, DD, nullptr, nullptr);
    gemm_nt<2><<<grid_d, blk>>>(hbuf, l2_w, l2_b, y, MM, DD, FF, x, alpha_ff);
    ln_kernel<<<MM, 256>>>(y, n2_s, n2_b, (float*)d_out);
}

// round 8
// speedup vs baseline: 2.0708x; 1.6028x over previous
#include <cuda_runtime.h>
#include <cuda_bf16.h>
#include <math.h>
#include <stdint.h>

// Problem constants
#define BB 2
#define TT 2048
#define DD 1024
#define HH 16
#define DHH 64
#define FF 4096
#define MM (BB*TT)          // 4096 rows

typedef unsigned long long ull;

// ---------------------------------------------------------------------------
// Baseline-PTX tensor helpers (sm_80-era: mma.sync / ldmatrix / cp.async)
// ---------------------------------------------------------------------------
__device__ __forceinline__ uint32_t smem_u32(const void* p) {
    uint32_t a;
    asm("{ .reg .u64 t; cvta.to.shared.u64 t, %1; cvt.u32.u64 %0, t; }" : "=r"(a) : "l"(p));
    return a;
}
__device__ __forceinline__ void cpa16(uint32_t dst, const void* src) {
    asm volatile("cp.async.cg.shared.global [%0], [%1], 16;" :: "r"(dst), "l"(src) : "memory");
}
#define CP_COMMIT() asm volatile("cp.async.commit_group;" ::: "memory")
#define CP_WAIT0()  asm volatile("cp.async.wait_group 0;" ::: "memory")

#define LDM4(r, a) \
    asm volatile("ldmatrix.sync.aligned.m8n8.x4.shared.b16 {%0,%1,%2,%3}, [%4];" \
        : "=r"((r)[0]), "=r"((r)[1]), "=r"((r)[2]), "=r"((r)[3]) : "r"(a))

__device__ __forceinline__ void mma16816(float* d, const uint32_t* a, const uint32_t* b) {
    asm volatile("mma.sync.aligned.m16n8k16.row.col.f32.bf16.bf16.f32 "
        "{%0,%1,%2,%3}, {%4,%5,%6,%7}, {%8,%9}, {%0,%1,%2,%3};"
        : "+f"(d[0]), "+f"(d[1]), "+f"(d[2]), "+f"(d[3])
        : "r"(a[0]), "r"(a[1]), "r"(a[2]), "r"(a[3]), "r"(b[0]), "r"(b[1]));
}

// ---------------------------------------------------------------------------
// Scratch (allocation-free: __device__ globals)
// ---------------------------------------------------------------------------
__device__ float g_q[MM*DD];
__device__ float g_k[MM*DD];
__device__ float g_v[MM*DD];
__device__ float g_attn[MM*DD];
__device__ float g_y[MM*DD];
__device__ float g_x[MM*DD];
__device__ float g_h[MM*FF];
__device__ unsigned char g_mask[TT*TT];
__device__ int g_mask_mode;

// bf16 split buffers
__device__ __nv_bfloat16 g_actH[MM*DD],  g_actL[MM*DD];   // src / attn / x (sequential reuse)
__device__ __nv_bfloat16 g_hH[MM*FF],    g_hL[MM*FF];
__device__ __nv_bfloat16 g_qwH[DD*DD],   g_qwL[DD*DD];
__device__ __nv_bfloat16 g_kwH[DD*DD],   g_kwL[DD*DD];
__device__ __nv_bfloat16 g_vwH[DD*DD],   g_vwL[DD*DD];
__device__ __nv_bfloat16 g_owH[DD*DD],   g_owL[DD*DD];
__device__ __nv_bfloat16 g_l1H[FF*DD],   g_l1L[FF*DD];
__device__ __nv_bfloat16 g_l2H[DD*FF],   g_l2L[DD*FF];

// ---------------------------------------------------------------------------
// fp32 -> (hi, lo) bf16 split
// ---------------------------------------------------------------------------
__global__ __launch_bounds__(256)
void split_kernel(const float* __restrict__ x, __nv_bfloat16* __restrict__ hi,
                  __nv_bfloat16* __restrict__ lo, int n4)
{
    int i = blockIdx.x * 256 + threadIdx.x;
    if (i >= n4) return;
    float4 v = ((const float4*)x)[i];
    __nv_bfloat16 h0 = __float2bfloat16(v.x), h1 = __float2bfloat16(v.y);
    __nv_bfloat16 h2 = __float2bfloat16(v.z), h3 = __float2bfloat16(v.w);
    __nv_bfloat16 l0 = __float2bfloat16(v.x - __bfloat162float(h0));
    __nv_bfloat16 l1 = __float2bfloat16(v.y - __bfloat162float(h1));
    __nv_bfloat16 l2 = __float2bfloat16(v.z - __bfloat162float(h2));
    __nv_bfloat16 l3 = __float2bfloat16(v.w - __bfloat162float(h3));
    __nv_bfloat162 ph0; ph0.x = h0; ph0.y = h1;
    __nv_bfloat162 ph1; ph1.x = h2; ph1.y = h3;
    __nv_bfloat162 pl0; pl0.x = l0; pl0.y = l1;
    __nv_bfloat162 pl1; pl1.x = l2; pl1.y = l3;
    ((__nv_bfloat162*)hi)[2*i]   = ph0;
    ((__nv_bfloat162*)hi)[2*i+1] = ph1;
    ((__nv_bfloat162*)lo)[2*i]   = pl0;
    ((__nv_bfloat162*)lo)[2*i+1] = pl1;
}

// ---------------------------------------------------------------------------
// Mask dtype detection + canonicalization to uint8
// ---------------------------------------------------------------------------
__global__ __launch_bounds__(1024)
void mask_scan_kernel(const uint32_t* __restrict__ m)
{
    const int tid = threadIdx.x;
    int u8f = 0, f32f = 0;
    const int NW = (TT*TT) / 4;
    for (int i = tid; i < NW; i += 1024) {
        uint32_t w = m[i];
        if (w != 0u && w != 1u && w != 0x3F800000u) u8f = 1;
        if (w == 0x3F800000u) f32f = 1;
    }
    __shared__ int s_u8, s_f32;
    if (tid == 0) { s_u8 = 0; s_f32 = 0; }
    __syncthreads();
    if (u8f)  atomicOr(&s_u8, 1);
    if (f32f) atomicOr(&s_f32, 1);
    __syncthreads();
    if (tid == 0)
        g_mask_mode = s_u8 ? 0 : (s_f32 ? 2 : 1);
}

__global__ __launch_bounds__(256)
void mask_convert_kernel(const void* __restrict__ min)
{
    const int mode = g_mask_mode;
    int i = blockIdx.x * blockDim.x + threadIdx.x;
    const int NW = (TT*TT) / 4;
    if (i >= NW) return;
    uint32_t out;
    if (mode == 0) {
        out = ((const uint32_t*)min)[i];
    } else if (mode == 1) {
        const int* p = (const int*)min;
        out  = (uint32_t)(p[4*i+0] != 0);
        out |= (uint32_t)(p[4*i+1] != 0) << 8;
        out |= (uint32_t)(p[4*i+2] != 0) << 16;
        out |= (uint32_t)(p[4*i+3] != 0) << 24;
    } else {
        const float* p = (const float*)min;
        out  = (uint32_t)(p[4*i+0] != 0.f);
        out |= (uint32_t)(p[4*i+1] != 0.f) << 8;
        out |= (uint32_t)(p[4*i+2] != 0.f) << 16;
        out |= (uint32_t)(p[4*i+3] != 0.f) << 24;
    }
    ((uint32_t*)g_mask)[i] = out;
}

// ---------------------------------------------------------------------------
// bf16-split GEMM via mma.sync: C[m,n] = sum_k A[m,k]*W[n,k] + bias[n]
// A ~ Ah+Al, W ~ Bh+Bl; computes Ah*Bh + Ah*Bl + Al*Bh, fp32 accumulate.
// 128x128 CTA tile, BK=64, 8 warps (2x4), warp tile 64x32.
// Double-buffered cp.async staging of 4 operand tiles (Ah/Al/Bh/Bl).
// EPI = 0: none, 1: relu, 2: res + alpha * (.)
// ---------------------------------------------------------------------------
#define TILE_B   16384                 // 128 rows x 128 bytes (64 bf16)
#define STAGE_B  (4*TILE_B)            // Ah, Al, Bh, Bl
#define GSM_DYN  (2*STAGE_B + 1024)

template<int EPI>
__global__ __launch_bounds__(256, 1)
void gemm_mma(const __nv_bfloat16* __restrict__ Ah, const __nv_bfloat16* __restrict__ Al,
              const __nv_bfloat16* __restrict__ Bh, const __nv_bfloat16* __restrict__ Bl,
              const float* __restrict__ bias, float* __restrict__ C,
              int M, int N, int K,
              const float* __restrict__ res, const float* __restrict__ alpha_p)
{
    extern __shared__ unsigned char sm[];
    const uint32_t smu  = smem_u32(sm);
    const uint32_t base = (smu + 1023) & ~1023u;

    const int tid  = threadIdx.x;
    const int wid  = tid >> 5;
    const int lane = tid & 31;
    const int wm   = wid >> 2;          // 0..1  (m block of 64)
    const int wn   = wid & 3;           // 0..3  (n block of 32)
    const int bm   = blockIdx.y * 128;
    const int bn   = blockIdx.x * 128;

    float d[4][4][4];                   // [mt][nt][frag]
    #pragma unroll
    for (int i = 0; i < 4; i++)
        #pragma unroll
        for (int j = 0; j < 4; j++)
            #pragma unroll
            for (int q = 0; q < 4; q++) d[i][j][q] = 0.f;

    // Staging map: s in [0,1024): row = s>>3 (0..127), c = s&7 (16B chunk)
    const int srow = tid >> 1;
    // each thread stages 4 chunks: c = (tid&1)*4 + 0..3 of its row
    const int sc0  = (tid & 1) * 4;
    const uint32_t swrowbase = (uint32_t)srow * 128;
    const int rx = srow & 7;

    const int NC = K >> 6;   // k-chunks of 64

    // Prologue: stage chunk 0 into buffer 0
    {
        const uint32_t st = base;
        #pragma unroll
        for (int j = 0; j < 4; j++) {
            const int c = sc0 + j;
            const uint32_t sw = swrowbase + ((uint32_t)(c ^ rx) << 4);
            const size_t goA = (size_t)(bm + srow) * K + c * 8;
            const size_t goB = (size_t)(bn + srow) * K + c * 8;
            cpa16(st + 0*TILE_B + sw, Ah + goA);
            cpa16(st + 1*TILE_B + sw, Al + goA);
            cpa16(st + 2*TILE_B + sw, Bh + goB);
            cpa16(st + 3*TILE_B + sw, Bl + goB);
        }
        CP_COMMIT();
    }

    for (int ch = 0; ch < NC; ch++) {
        CP_WAIT0();
        __syncthreads();

        // stage next chunk into other buffer
        if (ch + 1 < NC) {
            const uint32_t st = base + ((ch + 1) & 1) * STAGE_B;
            const size_t k0 = (size_t)(ch + 1) * 64;
            #pragma unroll
            for (int j = 0; j < 4; j++) {
                const int c = sc0 + j;
                const uint32_t sw = swrowbase + ((uint32_t)(c ^ rx) << 4);
                const size_t goA = (size_t)(bm + srow) * K + k0 + c * 8;
                const size_t goB = (size_t)(bn + srow) * K + k0 + c * 8;
                cpa16(st + 0*TILE_B + sw, Ah + goA);
                cpa16(st + 1*TILE_B + sw, Al + goA);
                cpa16(st + 2*TILE_B + sw, Bh + goB);
                cpa16(st + 3*TILE_B + sw, Bl + goB);
            }
            CP_COMMIT();
        }

        // compute on current buffer
        const uint32_t st = base + (ch & 1) * STAGE_B;
        const uint32_t aHs = st, aLs = st + TILE_B, bHs = st + 2*TILE_B, bLs = st + 3*TILE_B;

        // ldmatrix address offsets
        // A: row = wm*64 + mt*16 + (lane&15), khalf = lane>>4
        const int arow_base = wm * 64 + (lane & 15);
        const int akh = lane >> 4;             // 0/1
        // B: n = wn*32 + bt*16 + (lane&7) + ((lane>>4)<<3), khalf = (lane>>3)&1
        const int brow_base = wn * 32 + (lane & 7) + ((lane >> 4) << 3);
        const int bkh = (lane >> 3) & 1;

        #pragma unroll
        for (int k16 = 0; k16 < 4; k16++) {
            uint32_t ah[4][4], al[4][4], bh[2][4], bl[2][4];
            #pragma unroll
            for (int mt = 0; mt < 4; mt++) {
                const int row = arow_base + mt * 16;
                const uint32_t cb = (uint32_t)(k16 * 32 + akh * 16);
                const uint32_t off = (uint32_t)row * 128 + (cb ^ ((uint32_t)(row & 7) << 4));
                LDM4(ah[mt], aHs + off);
                LDM4(al[mt], aLs + off);
            }
            #pragma unroll
            for (int bt = 0; bt < 2; bt++) {
                const int row = brow_base + bt * 16;
                const uint32_t cb = (uint32_t)(k16 * 32 + bkh * 16);
                const uint32_t off = (uint32_t)row * 128 + (cb ^ ((uint32_t)(row & 7) << 4));
                LDM4(bh[bt], bHs + off);
                LDM4(bl[bt], bLs + off);
            }
            #pragma unroll
            for (int mt = 0; mt < 4; mt++) {
                #pragma unroll
                for (int nt = 0; nt < 4; nt++) {
                    const uint32_t* bhp = &bh[nt >> 1][(nt & 1) * 2];
                    const uint32_t* blp = &bl[nt >> 1][(nt & 1) * 2];
                    mma16816(d[mt][nt], ah[mt], bhp);   // hi*hi
                    mma16816(d[mt][nt], ah[mt], blp);   // hi*lo
                    mma16816(d[mt][nt], al[mt], bhp);   // lo*hi
                }
            }
        }
        __syncthreads();
    }

    // Epilogue
    float alpha = 0.f;
    if (EPI == 2) alpha = *alpha_p;
    const int g  = lane >> 2;
    const int nq = (lane & 3) * 2;

    #pragma unroll
    for (int mt = 0; mt < 4; mt++) {
        const int m0 = bm + wm * 64 + mt * 16 + g;
        #pragma unroll
        for (int nt = 0; nt < 4; nt++) {
            const int n = bn + wn * 32 + nt * 8 + nq;
            float2 b2 = *(const float2*)&bias[n];
            float2 o0 = make_float2(d[mt][nt][0] + b2.x, d[mt][nt][1] + b2.y);
            float2 o1 = make_float2(d[mt][nt][2] + b2.x, d[mt][nt][3] + b2.y);
            if (EPI == 1) {
                o0.x = fmaxf(o0.x, 0.f); o0.y = fmaxf(o0.y, 0.f);
                o1.x = fmaxf(o1.x, 0.f); o1.y = fmaxf(o1.y, 0.f);
            }
            if (EPI == 2) {
                float2 r0 = *(const float2*)&res[(size_t)m0 * N + n];
                float2 r1 = *(const float2*)&res[(size_t)(m0 + 8) * N + n];
                o0.x = r0.x + alpha * o0.x; o0.y = r0.y + alpha * o0.y;
                o1.x = r1.x + alpha * o1.x; o1.y = r1.y + alpha * o1.y;
            }
            *(float2*)&C[(size_t)m0 * N + n]       = o0;
            *(float2*)&C[(size_t)(m0 + 8) * N + n] = o1;
        }
    }
}

// ---------------------------------------------------------------------------
// Flash attention (fp32, FFMA2 inner loops) — unchanged from R4
// ---------------------------------------------------------------------------
__device__ __forceinline__ ull fdup(float x) {
    ull r;
    asm("mov.b64 %0, {%1, %1};" : "=l"(r) : "r"(__float_as_uint(x)));
    return r;
}
__device__ __forceinline__ void ffma2(ull& d, ull a, ull b) {
    asm("fma.rn.f32x2 %0, %1, %2, %0;" : "+l"(d) : "l"(a), "l"(b));
}
__device__ __forceinline__ void fmul2(ull& d, ull a) {
    asm("mul.rn.f32x2 %0, %0, %1;" : "+l"(d) : "l"(a));
}
__device__ __forceinline__ float2 unpk(ull v) {
    uint32_t lo, hi;
    asm("mov.b64 {%0, %1}, %2;" : "=r"(lo), "=r"(hi) : "l"(v));
    return make_float2(__uint_as_float(lo), __uint_as_float(hi));
}

#define FAS 68
#define FLASH_SMEM (4*64*FAS*4 + 64*64)

__global__ __launch_bounds__(256)
void flash_attn(const float* __restrict__ Q, const float* __restrict__ Kb,
                const float* __restrict__ Vb, const unsigned char* __restrict__ mask,
                float* __restrict__ O)
{
    extern __shared__ unsigned char sm_raw[];
    float* Qst = (float*)sm_raw;
    float* Kst = Qst + 64*FAS;
    float* Vs  = Kst + 64*FAS;
    float* Ps  = Vs  + 64*FAS;
    unsigned char* Ms = (unsigned char*)(Ps + 64*FAS);

    const int q0 = blockIdx.x * 64;
    const int h  = blockIdx.y;
    const int b  = blockIdx.z;
    const int tid = threadIdx.x;
    const int tx = tid & 15;
    const int ty = tid >> 4;

    const size_t base = ((size_t)b * TT) * DD + h * DHH;
    const float scale = 0.125f;

    #pragma unroll
    for (int u = 0; u < 4; u++) {
        int idx = tid + u * 256;
        int r = idx >> 4;
        int d0 = (idx & 15) << 2;
        float4 q = *(const float4*)&Q[base + (size_t)(q0 + r) * DD + d0];
        Qst[(d0+0)*FAS + r] = q.x; Qst[(d0+1)*FAS + r] = q.y;
        Qst[(d0+2)*FAS + r] = q.z; Qst[(d0+3)*FAS + r] = q.w;
    }

    float m_i[4], l_i[4];
    ull acc2[4][2];
    #pragma unroll
    for (int i = 0; i < 4; i++) {
        m_i[i] = -1e30f; l_i[i] = 0.f;
        acc2[i][0] = 0ull; acc2[i][1] = 0ull;
    }

    for (int s0 = 0; s0 < TT; s0 += 64) {
        __syncthreads();

        #pragma unroll
        for (int u = 0; u < 4; u++) {
            int idx = tid + u * 256;
            int s = idx >> 4;
            int d0 = (idx & 15) << 2;
            float4 kv = *(const float4*)&Kb[base + (size_t)(s0 + s) * DD + d0];
            Kst[(d0+0)*FAS + s] = kv.x; Kst[(d0+1)*FAS + s] = kv.y;
            Kst[(d0+2)*FAS + s] = kv.z; Kst[(d0+3)*FAS + s] = kv.w;
            float4 vv = *(const float4*)&Vb[base + (size_t)(s0 + s) * DD + d0];
            Vs[s*FAS + d0+0] = vv.x; Vs[s*FAS + d0+1] = vv.y;
            Vs[s*FAS + d0+2] = vv.z; Vs[s*FAS + d0+3] = vv.w;
        }
        {
            int mr = tid >> 2;
            int mc = (tid & 3) << 4;
            int4 mv = *(const int4*)&mask[(size_t)(q0 + mr) * TT + s0 + mc];
            *(int4*)&Ms[mr*64 + mc] = mv;
        }
        __syncthreads();

        ull sacc2[4][2];
        #pragma unroll
        for (int i = 0; i < 4; i++) { sacc2[i][0] = 0ull; sacc2[i][1] = 0ull; }
        #pragma unroll
        for (int d = 0; d < 64; d++) {
            float4 q4 = *(const float4*)&Qst[d*FAS + ty*4];
            ulonglong2 k2 = *(const ulonglong2*)&Kst[d*FAS + tx*4];
            ull qd[4];
            qd[0] = fdup(q4.x); qd[1] = fdup(q4.y); qd[2] = fdup(q4.z); qd[3] = fdup(q4.w);
            #pragma unroll
            for (int i = 0; i < 4; i++) {
                ffma2(sacc2[i][0], qd[i], k2.x);
                ffma2(sacc2[i][1], qd[i], k2.y);
            }
        }

        #pragma unroll
        for (int i = 0; i < 4; i++) {
            int r = ty*4 + i;
            float2 s01 = unpk(sacc2[i][0]);
            float2 s23 = unpk(sacc2[i][1]);
            float sac[4] = { s01.x, s01.y, s23.x, s23.y };
            bool msk[4];
            float sv[4];
            float tm = -1e30f;
            #pragma unroll
            for (int j = 0; j < 4; j++) {
                msk[j] = Ms[r*64 + tx*4 + j] != 0;
                sv[j] = msk[j] ? -1e30f : sac[j] * scale;
                tm = fmaxf(tm, sv[j]);
            }
            #pragma unroll
            for (int off = 8; off >= 1; off >>= 1)
                tm = fmaxf(tm, __shfl_xor_sync(0xffffffffu, tm, off));

            float mnew = fmaxf(m_i[i], tm);
            float af = __expf(m_i[i] - mnew);
            float rs = 0.f;
            #pragma unroll
            for (int j = 0; j < 4; j++) {
                float p = msk[j] ? 0.f : __expf(sv[j] - mnew);
                Ps[(tx*4 + j)*FAS + r] = p;
                rs += p;
            }
            #pragma unroll
            for (int off = 8; off >= 1; off >>= 1)
                rs += __shfl_xor_sync(0xffffffffu, rs, off);

            l_i[i] = af * l_i[i] + rs;
            m_i[i] = mnew;
            ull afd = fdup(af);
            fmul2(acc2[i][0], afd);
            fmul2(acc2[i][1], afd);
        }
        __syncthreads();

        #pragma unroll
        for (int s = 0; s < 64; s++) {
            float4 p4 = *(const float4*)&Ps[s*FAS + ty*4];
            ulonglong2 v2 = *(const ulonglong2*)&Vs[s*FAS + tx*4];
            ull pd[4];
            pd[0] = fdup(p4.x); pd[1] = fdup(p4.y); pd[2] = fdup(p4.z); pd[3] = fdup(p4.w);
            #pragma unroll
            for (int i = 0; i < 4; i++) {
                ffma2(acc2[i][0], pd[i], v2.x);
                ffma2(acc2[i][1], pd[i], v2.y);
            }
        }
    }

    #pragma unroll
    for (int i = 0; i < 4; i++) {
        float inv = (l_i[i] > 0.f) ? 1.f / l_i[i] : 0.f;
        int r = q0 + ty*4 + i;
        float2 o0 = unpk(acc2[i][0]);
        float2 o1 = unpk(acc2[i][1]);
        float4 o = make_float4(o0.x * inv, o0.y * inv, o1.x * inv, o1.y * inv);
        *(float4*)&O[base + (size_t)r * DD + tx*4] = o;
    }
}

// ---------------------------------------------------------------------------
// Row LayerNorm
// ---------------------------------------------------------------------------
__global__ __launch_bounds__(256)
void ln_kernel(const float* __restrict__ Y, const float* __restrict__ sc,
               const float* __restrict__ bi, float* __restrict__ X)
{
    const int row = blockIdx.x;
    const int tid = threadIdx.x;
    const float4 v = ((const float4*)(Y + (size_t)row * DD))[tid];

    float s  = v.x + v.y + v.z + v.w;
    float ss = v.x*v.x + v.y*v.y + v.z*v.z + v.w*v.w;
    #pragma unroll
    for (int off = 16; off >= 1; off >>= 1) {
        s  += __shfl_xor_sync(0xffffffffu, s,  off);
        ss += __shfl_xor_sync(0xffffffffu, ss, off);
    }

    __shared__ float ws[8], wss[8];
    __shared__ float mean_sh, rstd_sh;
    if ((tid & 31) == 0) { ws[tid >> 5] = s; wss[tid >> 5] = ss; }
    __syncthreads();
    if (tid == 0) {
        float S = 0.f, SS = 0.f;
        #pragma unroll
        for (int k = 0; k < 8; k++) { S += ws[k]; SS += wss[k]; }
        float mu = S / (float)DD;
        float var = SS / (float)DD - mu * mu;
        mean_sh = mu;
        rstd_sh = rsqrtf(var + 1e-5f);
    }
    __syncthreads();
    const float mu = mean_sh, rs = rstd_sh;

    const float4 sc4 = ((const float4*)sc)[tid];
    const float4 b4  = ((const float4*)bi)[tid];
    float4 o;
    o.x = (v.x - mu) * rs * sc4.x + b4.x;
    o.y = (v.y - mu) * rs * sc4.y + b4.y;
    o.z = (v.z - mu) * rs * sc4.z + b4.z;
    o.w = (v.w - mu) * rs * sc4.w + b4.w;
    ((float4*)(X + (size_t)row * DD))[tid] = o;
}

// ---------------------------------------------------------------------------
// Launch
// ---------------------------------------------------------------------------
extern "C" void kernel_launch(void* const* d_in, const int* in_sizes, int n_in,
                              void* d_out, int out_size)
{
    const float* src  = (const float*)d_in[0];
    const void*  mask_raw = d_in[1];
    const float* q_w = (const float*)d_in[2];
    const float* q_b = (const float*)d_in[3];
    const float* k_w = (const float*)d_in[4];
    const float* k_b = (const float*)d_in[5];
    const float* v_w = (const float*)d_in[6];
    const float* v_b = (const float*)d_in[7];
    const float* o_w = (const float*)d_in[8];
    const float* o_b = (const float*)d_in[9];
    const float* l1_w = (const float*)d_in[10];
    const float* l1_b = (const float*)d_in[11];
    const float* l2_w = (const float*)d_in[12];
    const float* l2_b = (const float*)d_in[13];
    const float* n1_s = (const float*)d_in[14];
    const float* n1_b = (const float*)d_in[15];
    const float* n2_s = (const float*)d_in[16];
    const float* n2_b = (const float*)d_in[17];
    const float* alpha_attn = (const float*)d_in[18];
    const float* alpha_ff   = (const float*)d_in[19];

    float *q, *k, *v, *attn, *y, *x, *hbuf;
    unsigned char* maskc;
    __nv_bfloat16 *actH, *actL, *hH, *hL;
    __nv_bfloat16 *qwH, *qwL, *kwH, *kwL, *vwH, *vwL, *owH, *owL, *l1H, *l1L, *l2H, *l2L;
    cudaGetSymbolAddress((void**)&q,    g_q);
    cudaGetSymbolAddress((void**)&k,    g_k);
    cudaGetSymbolAddress((void**)&v,    g_v);
    cudaGetSymbolAddress((void**)&attn, g_attn);
    cudaGetSymbolAddress((void**)&y,    g_y);
    cudaGetSymbolAddress((void**)&x,    g_x);
    cudaGetSymbolAddress((void**)&hbuf, g_h);
    cudaGetSymbolAddress((void**)&maskc, g_mask);
    cudaGetSymbolAddress((void**)&actH, g_actH);
    cudaGetSymbolAddress((void**)&actL, g_actL);
    cudaGetSymbolAddress((void**)&hH,   g_hH);
    cudaGetSymbolAddress((void**)&hL,   g_hL);
    cudaGetSymbolAddress((void**)&qwH,  g_qwH);
    cudaGetSymbolAddress((void**)&qwL,  g_qwL);
    cudaGetSymbolAddress((void**)&kwH,  g_kwH);
    cudaGetSymbolAddress((void**)&kwL,  g_kwL);
    cudaGetSymbolAddress((void**)&vwH,  g_vwH);
    cudaGetSymbolAddress((void**)&vwL,  g_vwL);
    cudaGetSymbolAddress((void**)&owH,  g_owH);
    cudaGetSymbolAddress((void**)&owL,  g_owL);
    cudaGetSymbolAddress((void**)&l1H,  g_l1H);
    cudaGetSymbolAddress((void**)&l1L,  g_l1L);
    cudaGetSymbolAddress((void**)&l2H,  g_l2H);
    cudaGetSymbolAddress((void**)&l2L,  g_l2L);

    cudaFuncSetAttribute(gemm_mma<0>, cudaFuncAttributeMaxDynamicSharedMemorySize, GSM_DYN);
    cudaFuncSetAttribute(gemm_mma<1>, cudaFuncAttributeMaxDynamicSharedMemorySize, GSM_DYN);
    cudaFuncSetAttribute(gemm_mma<2>, cudaFuncAttributeMaxDynamicSharedMemorySize, GSM_DYN);
    cudaFuncSetAttribute(flash_attn, cudaFuncAttributeMaxDynamicSharedMemorySize, FLASH_SMEM);

    dim3 blk(256);
    dim3 grid_qkv(DD/128, MM/128);    // (8, 32)
    dim3 grid_ff1(FF/128, MM/128);    // (32, 32)

    // Mask canonicalization
    mask_scan_kernel<<<1, 1024>>>((const uint32_t*)mask_raw);
    mask_convert_kernel<<<(TT*TT/4 + 255)/256, 256>>>(mask_raw);

    // Weight splits
    split_kernel<<<(DD*DD/4 + 255)/256, 256>>>(q_w, qwH, qwL, DD*DD/4);
    split_kernel<<<(DD*DD/4 + 255)/256, 256>>>(k_w, kwH, kwL, DD*DD/4);
    split_kernel<<<(DD*DD/4 + 255)/256, 256>>>(v_w, vwH, vwL, DD*DD/4);
    split_kernel<<<(DD*DD/4 + 255)/256, 256>>>(o_w, owH, owL, DD*DD/4);
    split_kernel<<<(FF*DD/4 + 255)/256, 256>>>(l1_w, l1H, l1L, FF*DD/4);
    split_kernel<<<(DD*FF/4 + 255)/256, 256>>>(l2_w, l2H, l2L, DD*FF/4);

    // QKV projections
    split_kernel<<<(MM*DD/4 + 255)/256, 256>>>(src, actH, actL, MM*DD/4);
    gemm_mma<0><<<grid_qkv, blk, GSM_DYN>>>(actH, actL, qwH, qwL, q_b, q, MM, DD, DD, nullptr, nullptr);
    gemm_mma<0><<<grid_qkv, blk, GSM_DYN>>>(actH, actL, kwH, kwL, k_b, k, MM, DD, DD, nullptr, nullptr);
    gemm_mma<0><<<grid_qkv, blk, GSM_DYN>>>(actH, actL, vwH, vwL, v_b, v, MM, DD, DD, nullptr, nullptr);

    // Flash attention
    flash_attn<<<dim3(TT/64, HH, BB), blk, FLASH_SMEM>>>(q, k, v, maskc, attn);

    // O projection + residual, LN1
    split_kernel<<<(MM*DD/4 + 255)/256, 256>>>(attn, actH, actL, MM*DD/4);
    gemm_mma<2><<<grid_qkv, blk, GSM_DYN>>>(actH, actL, owH, owL, o_b, y, MM, DD, DD, src, alpha_attn);
    ln_kernel<<<MM, 256>>>(y, n1_s, n1_b, x);

    // FFN
    split_kernel<<<(MM*DD/4 + 255)/256, 256>>>(x, actH, actL, MM*DD/4);
    gemm_mma<1><<<grid_ff1, blk, GSM_DYN>>>(actH, actL, l1H, l1L, l1_b, hbuf, MM, FF, DD, nullptr, nullptr);
    split_kernel<<<(MM*FF/4 + 255)/256, 256>>>(hbuf, hH, hL, MM*FF/4);
    gemm_mma<2><<<grid_qkv, blk, GSM_DYN>>>(hH, hL, l2H, l2L, l2_b, y, MM, DD, FF, x, alpha_ff);
    ln_kernel<<<MM, 256>>>(y, n2_s, n2_b, (float*)d_out);
}

// round 9
// speedup vs baseline: 3.3273x; 1.6068x over previous
#include <cuda_runtime.h>
#include <cuda_bf16.h>
#include <math.h>
#include <stdint.h>

// Problem constants
#define BB 2
#define TT 2048
#define DD 1024
#define HH 16
#define DHH 64
#define FF 4096
#define MM (BB*TT)          // 4096 rows

// ---------------------------------------------------------------------------
// Baseline-PTX tensor helpers (sm_80-era: mma.sync / ldmatrix / cp.async)
// ---------------------------------------------------------------------------
__device__ __forceinline__ uint32_t smem_u32(const void* p) {
    uint32_t a;
    asm("{ .reg .u64 t; cvta.to.shared.u64 t, %1; cvt.u32.u64 %0, t; }" : "=r"(a) : "l"(p));
    return a;
}
__device__ __forceinline__ void cpa16(uint32_t dst, const void* src) {
    asm volatile("cp.async.cg.shared.global [%0], [%1], 16;" :: "r"(dst), "l"(src) : "memory");
}
#define CP_COMMIT() asm volatile("cp.async.commit_group;" ::: "memory")
#define CP_WAIT0()  asm volatile("cp.async.wait_group 0;" ::: "memory")
#define CP_WAIT1()  asm volatile("cp.async.wait_group 1;" ::: "memory")

#define LDM4(r, a) \
    asm volatile("ldmatrix.sync.aligned.m8n8.x4.shared.b16 {%0,%1,%2,%3}, [%4];" \
        : "=r"((r)[0]), "=r"((r)[1]), "=r"((r)[2]), "=r"((r)[3]) : "r"(a))
#define LDM4T(r, a) \
    asm volatile("ldmatrix.sync.aligned.m8n8.x4.trans.shared.b16 {%0,%1,%2,%3}, [%4];" \
        : "=r"((r)[0]), "=r"((r)[1]), "=r"((r)[2]), "=r"((r)[3]) : "r"(a))

__device__ __forceinline__ void mma16816(float* d, const uint32_t* a, const uint32_t* b) {
    asm volatile("mma.sync.aligned.m16n8k16.row.col.f32.bf16.bf16.f32 "
        "{%0,%1,%2,%3}, {%4,%5,%6,%7}, {%8,%9}, {%0,%1,%2,%3};"
        : "+f"(d[0]), "+f"(d[1]), "+f"(d[2]), "+f"(d[3])
        : "r"(a[0]), "r"(a[1]), "r"(a[2]), "r"(a[3]), "r"(b[0]), "r"(b[1]));
}

// pack {lo, hi} floats into bf16x2 register (lo -> low half)
__device__ __forceinline__ uint32_t pkbf(float lo, float hi) {
    uint32_t d;
    asm("cvt.rn.bf16x2.f32 %0, %1, %2;" : "=r"(d) : "f"(hi), "f"(lo));
    return d;
}

// ---------------------------------------------------------------------------
// Scratch (allocation-free: __device__ globals)
// ---------------------------------------------------------------------------
__device__ float g_q[MM*DD];        // reused as bf16 q buffer
__device__ float g_k[MM*DD];        // reused as bf16 k buffer
__device__ float g_v[MM*DD];        // reused as bf16 v buffer
__device__ float g_y[MM*DD];
__device__ float g_x[MM*DD];
__device__ unsigned char g_mask[TT*TT];
__device__ int g_mask_mode;

// bf16 split buffers
__device__ __nv_bfloat16 g_actH[MM*DD],  g_actL[MM*DD];   // src split / attn split
__device__ __nv_bfloat16 g_xH[MM*DD],    g_xL[MM*DD];
__device__ __nv_bfloat16 g_hH[MM*FF],    g_hL[MM*FF];
__device__ __nv_bfloat16 g_qwH[DD*DD],   g_qwL[DD*DD];
__device__ __nv_bfloat16 g_kwH[DD*DD],   g_kwL[DD*DD];
__device__ __nv_bfloat16 g_vwH[DD*DD],   g_vwL[DD*DD];
__device__ __nv_bfloat16 g_owH[DD*DD],   g_owL[DD*DD];
__device__ __nv_bfloat16 g_l1H[FF*DD],   g_l1L[FF*DD];
__device__ __nv_bfloat16 g_l2H[DD*FF],   g_l2L[DD*FF];

// ---------------------------------------------------------------------------
// fp32 -> (hi, lo) bf16 split
// ---------------------------------------------------------------------------
__global__ __launch_bounds__(256)
void split_kernel(const float* __restrict__ x, __nv_bfloat16* __restrict__ hi,
                  __nv_bfloat16* __restrict__ lo, int n4)
{
    int i = blockIdx.x * 256 + threadIdx.x;
    if (i >= n4) return;
    float4 v = ((const float4*)x)[i];
    __nv_bfloat16 h0 = __float2bfloat16(v.x), h1 = __float2bfloat16(v.y);
    __nv_bfloat16 h2 = __float2bfloat16(v.z), h3 = __float2bfloat16(v.w);
    __nv_bfloat16 l0 = __float2bfloat16(v.x - __bfloat162float(h0));
    __nv_bfloat16 l1 = __float2bfloat16(v.y - __bfloat162float(h1));
    __nv_bfloat16 l2 = __float2bfloat16(v.z - __bfloat162float(h2));
    __nv_bfloat16 l3 = __float2bfloat16(v.w - __bfloat162float(h3));
    __nv_bfloat162 ph0; ph0.x = h0; ph0.y = h1;
    __nv_bfloat162 ph1; ph1.x = h2; ph1.y = h3;
    __nv_bfloat162 pl0; pl0.x = l0; pl0.y = l1;
    __nv_bfloat162 pl1; pl1.x = l2; pl1.y = l3;
    ((__nv_bfloat162*)hi)[2*i]   = ph0;
    ((__nv_bfloat162*)hi)[2*i+1] = ph1;
    ((__nv_bfloat162*)lo)[2*i]   = pl0;
    ((__nv_bfloat162*)lo)[2*i+1] = pl1;
}

// ---------------------------------------------------------------------------
// Mask dtype detection + canonicalization to uint8
// ---------------------------------------------------------------------------
__global__ __launch_bounds__(1024)
void mask_scan_kernel(const uint32_t* __restrict__ m)
{
    const int tid = threadIdx.x;
    int u8f = 0, f32f = 0;
    const int NW = (TT*TT) / 4;
    for (int i = tid; i < NW; i += 1024) {
        uint32_t w = m[i];
        if (w != 0u && w != 1u && w != 0x3F800000u) u8f = 1;
        if (w == 0x3F800000u) f32f = 1;
    }
    __shared__ int s_u8, s_f32;
    if (tid == 0) { s_u8 = 0; s_f32 = 0; }
    __syncthreads();
    if (u8f)  atomicOr(&s_u8, 1);
    if (f32f) atomicOr(&s_f32, 1);
    __syncthreads();
    if (tid == 0)
        g_mask_mode = s_u8 ? 0 : (s_f32 ? 2 : 1);
}

__global__ __launch_bounds__(256)
void mask_convert_kernel(const void* __restrict__ min)
{
    const int mode = g_mask_mode;
    int i = blockIdx.x * blockDim.x + threadIdx.x;
    const int NW = (TT*TT) / 4;
    if (i >= NW) return;
    uint32_t out;
    if (mode == 0) {
        out = ((const uint32_t*)min)[i];
    } else if (mode == 1) {
        const int* p = (const int*)min;
        out  = (uint32_t)(p[4*i+0] != 0);
        out |= (uint32_t)(p[4*i+1] != 0) << 8;
        out |= (uint32_t)(p[4*i+2] != 0) << 16;
        out |= (uint32_t)(p[4*i+3] != 0) << 24;
    } else {
        const float* p = (const float*)min;
        out  = (uint32_t)(p[4*i+0] != 0.f);
        out |= (uint32_t)(p[4*i+1] != 0.f) << 8;
        out |= (uint32_t)(p[4*i+2] != 0.f) << 16;
        out |= (uint32_t)(p[4*i+3] != 0.f) << 24;
    }
    ((uint32_t*)g_mask)[i] = out;
}

// ---------------------------------------------------------------------------
// bf16-split GEMM via mma.sync: acc = sum_k A[m,k]*W[n,k]  (3-term split)
// EPI: 0 = bias -> f32 C
//      1 = bias+relu -> f32 C
//      2 = res + alpha*(acc+bias) -> f32 C
//      3 = bias -> bf16 outH (plain bf16 output)
//      4 = bias+relu -> split bf16 (outH, outL)
// ---------------------------------------------------------------------------
#define TILE_B   16384                 // 128 rows x 128 bytes (64 bf16)
#define STAGE_B  (4*TILE_B)            // Ah, Al, Bh, Bl
#define GSM_DYN  (2*STAGE_B + 1024)

template<int EPI>
__global__ __launch_bounds__(256, 1)
void gemm_mma(const __nv_bfloat16* __restrict__ Ah, const __nv_bfloat16* __restrict__ Al,
              const __nv_bfloat16* __restrict__ Bh, const __nv_bfloat16* __restrict__ Bl,
              const float* __restrict__ bias, float* __restrict__ C,
              int M, int N, int K,
              const float* __restrict__ res, const float* __restrict__ alpha_p,
              __nv_bfloat16* __restrict__ outH, __nv_bfloat16* __restrict__ outL)
{
    extern __shared__ unsigned char sm[];
    const uint32_t smu  = smem_u32(sm);
    const uint32_t base = (smu + 1023) & ~1023u;

    const int tid  = threadIdx.x;
    const int wid  = tid >> 5;
    const int lane = tid & 31;
    const int wm   = wid >> 2;          // 0..1  (m block of 64)
    const int wn   = wid & 3;           // 0..3  (n block of 32)
    const int bm   = blockIdx.y * 128;
    const int bn   = blockIdx.x * 128;

    float d[4][4][4];
    #pragma unroll
    for (int i = 0; i < 4; i++)
        #pragma unroll
        for (int j = 0; j < 4; j++)
            #pragma unroll
            for (int q = 0; q < 4; q++) d[i][j][q] = 0.f;

    const int srow = tid >> 1;
    const int sc0  = (tid & 1) * 4;
    const uint32_t swrowbase = (uint32_t)srow * 128;
    const int rx = srow & 7;

    const int NC = K >> 6;

    {
        const uint32_t st = base;
        #pragma unroll
        for (int j = 0; j < 4; j++) {
            const int c = sc0 + j;
            const uint32_t sw = swrowbase + ((uint32_t)(c ^ rx) << 4);
            const size_t goA = (size_t)(bm + srow) * K + c * 8;
            const size_t goB = (size_t)(bn + srow) * K + c * 8;
            cpa16(st + 0*TILE_B + sw, Ah + goA);
            cpa16(st + 1*TILE_B + sw, Al + goA);
            cpa16(st + 2*TILE_B + sw, Bh + goB);
            cpa16(st + 3*TILE_B + sw, Bl + goB);
        }
        CP_COMMIT();
    }

    for (int ch = 0; ch < NC; ch++) {
        CP_WAIT0();
        __syncthreads();

        if (ch + 1 < NC) {
            const uint32_t st = base + ((ch + 1) & 1) * STAGE_B;
            const size_t k0 = (size_t)(ch + 1) * 64;
            #pragma unroll
            for (int j = 0; j < 4; j++) {
                const int c = sc0 + j;
                const uint32_t sw = swrowbase + ((uint32_t)(c ^ rx) << 4);
                const size_t goA = (size_t)(bm + srow) * K + k0 + c * 8;
                const size_t goB = (size_t)(bn + srow) * K + k0 + c * 8;
                cpa16(st + 0*TILE_B + sw, Ah + goA);
                cpa16(st + 1*TILE_B + sw, Al + goA);
                cpa16(st + 2*TILE_B + sw, Bh + goB);
                cpa16(st + 3*TILE_B + sw, Bl + goB);
            }
            CP_COMMIT();
        }

        const uint32_t st = base + (ch & 1) * STAGE_B;
        const uint32_t aHs = st, aLs = st + TILE_B, bHs = st + 2*TILE_B, bLs = st + 3*TILE_B;

        const int arow_base = wm * 64 + (lane & 15);
        const int akh = lane >> 4;
        const int brow_base = wn * 32 + (lane & 7) + ((lane >> 4) << 3);
        const int bkh = (lane >> 3) & 1;

        #pragma unroll
        for (int k16 = 0; k16 < 4; k16++) {
            uint32_t ah[4][4], al[4][4], bh[2][4], bl[2][4];
            #pragma unroll
            for (int mt = 0; mt < 4; mt++) {
                const int row = arow_base + mt * 16;
                const uint32_t cb = (uint32_t)(k16 * 32 + akh * 16);
                const uint32_t off = (uint32_t)row * 128 + (cb ^ ((uint32_t)(row & 7) << 4));
                LDM4(ah[mt], aHs + off);
                LDM4(al[mt], aLs + off);
            }
            #pragma unroll
            for (int bt = 0; bt < 2; bt++) {
                const int row = brow_base + bt * 16;
                const uint32_t cb = (uint32_t)(k16 * 32 + bkh * 16);
                const uint32_t off = (uint32_t)row * 128 + (cb ^ ((uint32_t)(row & 7) << 4));
                LDM4(bh[bt], bHs + off);
                LDM4(bl[bt], bLs + off);
            }
            #pragma unroll
            for (int mt = 0; mt < 4; mt++) {
                #pragma unroll
                for (int nt = 0; nt < 4; nt++) {
                    const uint32_t* bhp = &bh[nt >> 1][(nt & 1) * 2];
                    const uint32_t* blp = &bl[nt >> 1][(nt & 1) * 2];
                    mma16816(d[mt][nt], ah[mt], bhp);
                    mma16816(d[mt][nt], ah[mt], blp);
                    mma16816(d[mt][nt], al[mt], bhp);
                }
            }
        }
        __syncthreads();
    }

    // Epilogue
    float alpha = 0.f;
    if (EPI == 2) alpha = *alpha_p;
    const int g  = lane >> 2;
    const int nq = (lane & 3) * 2;

    #pragma unroll
    for (int mt = 0; mt < 4; mt++) {
        const int m0 = bm + wm * 64 + mt * 16 + g;
        #pragma unroll
        for (int nt = 0; nt < 4; nt++) {
            const int n = bn + wn * 32 + nt * 8 + nq;
            float2 b2 = *(const float2*)&bias[n];
            float2 o0 = make_float2(d[mt][nt][0] + b2.x, d[mt][nt][1] + b2.y);
            float2 o1 = make_float2(d[mt][nt][2] + b2.x, d[mt][nt][3] + b2.y);
            if (EPI == 1 || EPI == 4) {
                o0.x = fmaxf(o0.x, 0.f); o0.y = fmaxf(o0.y, 0.f);
                o1.x = fmaxf(o1.x, 0.f); o1.y = fmaxf(o1.y, 0.f);
            }
            if (EPI == 2) {
                float2 r0 = *(const float2*)&res[(size_t)m0 * N + n];
                float2 r1 = *(const float2*)&res[(size_t)(m0 + 8) * N + n];
                o0.x = r0.x + alpha * o0.x; o0.y = r0.y + alpha * o0.y;
                o1.x = r1.x + alpha * o1.x; o1.y = r1.y + alpha * o1.y;
            }
            if (EPI <= 2) {
                *(float2*)&C[(size_t)m0 * N + n]       = o0;
                *(float2*)&C[(size_t)(m0 + 8) * N + n] = o1;
            } else if (EPI == 3) {
                *(uint32_t*)&outH[(size_t)m0 * N + n]       = pkbf(o0.x, o0.y);
                *(uint32_t*)&outH[(size_t)(m0 + 8) * N + n] = pkbf(o1.x, o1.y);
            } else {  // EPI == 4: split store
                float h0 = __bfloat162float(__float2bfloat16(o0.x));
                float h1 = __bfloat162float(__float2bfloat16(o0.y));
                float h2 = __bfloat162float(__float2bfloat16(o1.x));
                float h3 = __bfloat162float(__float2bfloat16(o1.y));
                *(uint32_t*)&outH[(size_t)m0 * N + n]       = pkbf(h0, h1);
                *(uint32_t*)&outH[(size_t)(m0 + 8) * N + n] = pkbf(h2, h3);
                *(uint32_t*)&outL[(size_t)m0 * N + n]       = pkbf(o0.x - h0, o0.y - h1);
                *(uint32_t*)&outL[(size_t)(m0 + 8) * N + n] = pkbf(o1.x - h2, o1.y - h3);
            }
        }
    }
}

// ---------------------------------------------------------------------------
// Tensor-core flash attention (bf16 mma, fp32 softmax).
// CTA = 128 q-rows of one (b,h). s-tiles of 64 keys, cp.async double buffer.
// Output written as split bf16 (OH, OL) for the O-projection GEMM.
// ---------------------------------------------------------------------------
#define MPAD 80
#define KV_B  8192                       // 64 rows x 128B
#define MB_B  (128*MPAD)                 // 10240
#define BUF_B (2*KV_B + MB_B)            // 26624
#define ATT_SMEM (16384 + 2*BUF_B + 1024)

__global__ __launch_bounds__(256, 2)
void flash_attn_tc(const __nv_bfloat16* __restrict__ Qb, const __nv_bfloat16* __restrict__ Kb,
                   const __nv_bfloat16* __restrict__ Vb, const unsigned char* __restrict__ mask,
                   __nv_bfloat16* __restrict__ OH, __nv_bfloat16* __restrict__ OL)
{
    extern __shared__ unsigned char sm[];
    const uint32_t smu = smem_u32(sm);
    const uint32_t Qs  = (smu + 1023) & ~1023u;

    const int tid = threadIdx.x, wid = tid >> 5, lane = tid & 31;
    const int q0 = blockIdx.x * 128;
    const int h  = blockIdx.y, b = blockIdx.z;
    const size_t rowbase = (size_t)b * TT;
    const int colh = h * DHH;

    // ---- stage Q (128 rows x 128B) ----
    {
        const int r = tid >> 1, c0 = (tid & 1) * 4;
        const __nv_bfloat16* src = Qb + (rowbase + q0 + r) * DD + colh;
        #pragma unroll
        for (int j = 0; j < 4; j++) {
            const int c = c0 + j;
            cpa16(Qs + r * 128 + ((uint32_t)(c ^ (r & 7)) << 4), src + c * 8);
        }
    }
    // ---- stage tile 0 ----
    {
        const uint32_t Ks = Qs + 16384, Vs = Ks + KV_B, Ms = Vs + KV_B;
        const int r = tid >> 2;                 // 0..63
        const int j2 = tid & 3;
        #pragma unroll
        for (int j = 0; j < 2; j++) {
            const int c = j2 * 2 + j;
            const uint32_t sw = r * 128 + ((uint32_t)(c ^ (r & 7)) << 4);
            cpa16(Ks + sw, Kb + (rowbase + r) * DD + colh + c * 8);
            cpa16(Vs + sw, Vb + (rowbase + r) * DD + colh + c * 8);
        }
        const int mr = tid >> 1;
        #pragma unroll
        for (int j = 0; j < 2; j++) {
            const int c = (tid & 1) * 2 + j;
            cpa16(Ms + mr * MPAD + c * 16, mask + (size_t)(q0 + mr) * TT + c * 16);
        }
        CP_COMMIT();
    }

    // per-lane softmax state (rows r0 = lane>>2, r1 = r0+8 within warp's 16)
    float m0 = -1e30f, m1 = -1e30f, l0 = 0.f, l1 = 0.f;
    float o[8][4];
    #pragma unroll
    for (int i = 0; i < 8; i++)
        #pragma unroll
        for (int j = 0; j < 4; j++) o[i][j] = 0.f;

    uint32_t aQ[4][4];
    const int arow = wid * 16 + (lane & 15);
    const int akh  = lane >> 4;
    const int brow = (lane & 7) + ((lane >> 4) << 3);
    const int bkh  = (lane >> 3) & 1;
    const int r0   = lane >> 2;
    const int cq   = (lane & 3) * 2;

    const int NT = TT / 64;   // 32
    for (int st = 0; st < NT; st++) {
        // stage next tile
        if (st + 1 < NT) {
            const uint32_t base = Qs + 16384 + ((st + 1) & 1) * BUF_B;
            const uint32_t Ks = base, Vs = base + KV_B, Ms = base + 2*KV_B;
            const int s1 = (st + 1) * 64;
            const int r = tid >> 2, j2 = tid & 3;
            #pragma unroll
            for (int j = 0; j < 2; j++) {
                const int c = j2 * 2 + j;
                const uint32_t sw = r * 128 + ((uint32_t)(c ^ (r & 7)) << 4);
                cpa16(Ks + sw, Kb + (rowbase + s1 + r) * DD + colh + c * 8);
                cpa16(Vs + sw, Vb + (rowbase + s1 + r) * DD + colh + c * 8);
            }
            const int mr = tid >> 1;
            #pragma unroll
            for (int j = 0; j < 2; j++) {
                const int c = (tid & 1) * 2 + j;
                cpa16(Ms + mr * MPAD + c * 16, mask + (size_t)(q0 + mr) * TT + s1 + c * 16);
            }
            CP_COMMIT();
            CP_WAIT1();
        } else {
            CP_WAIT0();
        }
        __syncthreads();

        if (st == 0) {
            #pragma unroll
            for (int kt = 0; kt < 4; kt++) {
                const uint32_t cb = (uint32_t)(kt * 32 + akh * 16);
                LDM4(aQ[kt], Qs + (uint32_t)arow * 128 + (cb ^ ((uint32_t)(arow & 7) << 4)));
            }
        }

        const uint32_t base = Qs + 16384 + (st & 1) * BUF_B;
        const uint32_t Ks = base, Vs = base + KV_B, Ms = base + 2*KV_B;

        // ---- S = Q K^T ----
        float sacc[8][4];
        #pragma unroll
        for (int i = 0; i < 8; i++)
            #pragma unroll
            for (int j = 0; j < 4; j++) sacc[i][j] = 0.f;

        #pragma unroll
        for (int kt = 0; kt < 4; kt++) {
            uint32_t bK[4][4];
            #pragma unroll
            for (int bt = 0; bt < 4; bt++) {
                const int row = brow + bt * 16;
                const uint32_t cb = (uint32_t)(kt * 32 + bkh * 16);
                LDM4(bK[bt], Ks + (uint32_t)row * 128 + (cb ^ ((uint32_t)(row & 7) << 4)));
            }
            #pragma unroll
            for (int nt = 0; nt < 8; nt++)
                mma16816(sacc[nt], aQ[kt], &bK[nt >> 1][(nt & 1) * 2]);
        }

        // ---- masked online softmax ----
        const int mrow0 = wid * 16 + r0;
        float mx0 = -1e30f, mx1 = -1e30f;
        #pragma unroll
        for (int nt = 0; nt < 8; nt++) {
            uchar2 k0 = *(const uchar2*)(sm + (Ms - smu) + mrow0 * MPAD + nt * 8 + cq);
            uchar2 k1 = *(const uchar2*)(sm + (Ms - smu) + (mrow0 + 8) * MPAD + nt * 8 + cq);
            sacc[nt][0] = k0.x ? -1e30f : sacc[nt][0] * 0.125f;
            sacc[nt][1] = k0.y ? -1e30f : sacc[nt][1] * 0.125f;
            sacc[nt][2] = k1.x ? -1e30f : sacc[nt][2] * 0.125f;
            sacc[nt][3] = k1.y ? -1e30f : sacc[nt][3] * 0.125f;
            mx0 = fmaxf(mx0, fmaxf(sacc[nt][0], sacc[nt][1]));
            mx1 = fmaxf(mx1, fmaxf(sacc[nt][2], sacc[nt][3]));
        }
        mx0 = fmaxf(mx0, __shfl_xor_sync(0xffffffffu, mx0, 1));
        mx0 = fmaxf(mx0, __shfl_xor_sync(0xffffffffu, mx0, 2));
        mx1 = fmaxf(mx1, __shfl_xor_sync(0xffffffffu, mx1, 1));
        mx1 = fmaxf(mx1, __shfl_xor_sync(0xffffffffu, mx1, 2));

        const float mn0 = fmaxf(m0, mx0), mn1 = fmaxf(m1, mx1);
        const float af0 = __expf(m0 - mn0), af1 = __expf(m1 - mn1);
        float rs0 = 0.f, rs1 = 0.f;
        #pragma unroll
        for (int nt = 0; nt < 8; nt++) {
            float p0 = (sacc[nt][0] == -1e30f) ? 0.f : __expf(sacc[nt][0] - mn0);
            float p1 = (sacc[nt][1] == -1e30f) ? 0.f : __expf(sacc[nt][1] - mn0);
            float p2 = (sacc[nt][2] == -1e30f) ? 0.f : __expf(sacc[nt][2] - mn1);
            float p3 = (sacc[nt][3] == -1e30f) ? 0.f : __expf(sacc[nt][3] - mn1);
            sacc[nt][0] = p0; sacc[nt][1] = p1; sacc[nt][2] = p2; sacc[nt][3] = p3;
            rs0 += p0 + p1; rs1 += p2 + p3;
        }
        rs0 += __shfl_xor_sync(0xffffffffu, rs0, 1);
        rs0 += __shfl_xor_sync(0xffffffffu, rs0, 2);
        rs1 += __shfl_xor_sync(0xffffffffu, rs1, 1);
        rs1 += __shfl_xor_sync(0xffffffffu, rs1, 2);
        l0 = af0 * l0 + rs0;  m0 = mn0;
        l1 = af1 * l1 + rs1;  m1 = mn1;

        #pragma unroll
        for (int nt = 0; nt < 8; nt++) {
            o[nt][0] *= af0; o[nt][1] *= af0;
            o[nt][2] *= af1; o[nt][3] *= af1;
        }

        // pack P into A-fragments (m16k16 over s)
        uint32_t pf[4][4];
        #pragma unroll
        for (int kt = 0; kt < 4; kt++) {
            pf[kt][0] = pkbf(sacc[2*kt][0],   sacc[2*kt][1]);
            pf[kt][1] = pkbf(sacc[2*kt][2],   sacc[2*kt][3]);
            pf[kt][2] = pkbf(sacc[2*kt+1][0], sacc[2*kt+1][1]);
            pf[kt][3] = pkbf(sacc[2*kt+1][2], sacc[2*kt+1][3]);
        }

        // ---- O += P V ----
        #pragma unroll
        for (int kt = 0; kt < 4; kt++) {
            #pragma unroll
            for (int nt2 = 0; nt2 < 4; nt2++) {
                uint32_t bV[4];
                const int rv = kt * 16 + (lane & 15);
                const uint32_t c = (uint32_t)(nt2 * 2 + (lane >> 4));
                LDM4T(bV, Vs + (uint32_t)rv * 128 + ((c ^ (uint32_t)(rv & 7)) << 4));
                mma16816(o[2*nt2],     pf[kt], &bV[0]);
                mma16816(o[2*nt2 + 1], pf[kt], &bV[2]);
            }
        }
        __syncthreads();
    }

    // ---- epilogue: normalize + split bf16 store ----
    const float inv0 = (l0 > 0.f) ? 1.f / l0 : 0.f;
    const float inv1 = (l1 > 0.f) ? 1.f / l1 : 0.f;
    const size_t row0 = rowbase + q0 + wid * 16 + r0;
    #pragma unroll
    for (int nt = 0; nt < 8; nt++) {
        const int n = colh + nt * 8 + cq;
        float v0 = o[nt][0] * inv0, v1 = o[nt][1] * inv0;
        float v2 = o[nt][2] * inv1, v3 = o[nt][3] * inv1;
        float h0 = __bfloat162float(__float2bfloat16(v0));
        float h1 = __bfloat162float(__float2bfloat16(v1));
        float h2 = __bfloat162float(__float2bfloat16(v2));
        float h3 = __bfloat162float(__float2bfloat16(v3));
        *(uint32_t*)&OH[row0 * DD + n]       = pkbf(h0, h1);
        *(uint32_t*)&OH[(row0 + 8) * DD + n] = pkbf(h2, h3);
        *(uint32_t*)&OL[row0 * DD + n]       = pkbf(v0 - h0, v1 - h1);
        *(uint32_t*)&OL[(row0 + 8) * DD + n] = pkbf(v2 - h2, v3 - h3);
    }
}

// ---------------------------------------------------------------------------
// Row LayerNorm; SPLIT=1 additionally emits bf16 hi/lo split of the output.
// ---------------------------------------------------------------------------
template<int SPLIT>
__global__ __launch_bounds__(256)
void ln_kernel(const float* __restrict__ Y, const float* __restrict__ sc,
               const float* __restrict__ bi, float* __restrict__ X,
               __nv_bfloat16* __restrict__ outH, __nv_bfloat16* __restrict__ outL)
{
    const int row = blockIdx.x;
    const int tid = threadIdx.x;
    const float4 v = ((const float4*)(Y + (size_t)row * DD))[tid];

    float s  = v.x + v.y + v.z + v.w;
    float ss = v.x*v.x + v.y*v.y + v.z*v.z + v.w*v.w;
    #pragma unroll
    for (int off = 16; off >= 1; off >>= 1) {
        s  += __shfl_xor_sync(0xffffffffu, s,  off);
        ss += __shfl_xor_sync(0xffffffffu, ss, off);
    }

    __shared__ float ws[8], wss[8];
    __shared__ float mean_sh, rstd_sh;
    if ((tid & 31) == 0) { ws[tid >> 5] = s; wss[tid >> 5] = ss; }
    __syncthreads();
    if (tid == 0) {
        float S = 0.f, SS = 0.f;
        #pragma unroll
        for (int k = 0; k < 8; k++) { S += ws[k]; SS += wss[k]; }
        float mu = S / (float)DD;
        float var = SS / (float)DD - mu * mu;
        mean_sh = mu;
        rstd_sh = rsqrtf(var + 1e-5f);
    }
    __syncthreads();
    const float mu = mean_sh, rs = rstd_sh;

    const float4 sc4 = ((const float4*)sc)[tid];
    const float4 b4  = ((const float4*)bi)[tid];
    float4 o;
    o.x = (v.x - mu) * rs * sc4.x + b4.x;
    o.y = (v.y - mu) * rs * sc4.y + b4.y;
    o.z = (v.z - mu) * rs * sc4.z + b4.z;
    o.w = (v.w - mu) * rs * sc4.w + b4.w;
    ((float4*)(X + (size_t)row * DD))[tid] = o;

    if (SPLIT) {
        float h0 = __bfloat162float(__float2bfloat16(o.x));
        float h1 = __bfloat162float(__float2bfloat16(o.y));
        float h2 = __bfloat162float(__float2bfloat16(o.z));
        float h3 = __bfloat162float(__float2bfloat16(o.w));
        uint2 hv = make_uint2(pkbf(h0, h1), pkbf(h2, h3));
        uint2 lv = make_uint2(pkbf(o.x - h0, o.y - h1), pkbf(o.z - h2, o.w - h3));
        *(uint2*)&outH[(size_t)row * DD + tid * 4] = hv;
        *(uint2*)&outL[(size_t)row * DD + tid * 4] = lv;
    }
}

// ---------------------------------------------------------------------------
// Launch
// ---------------------------------------------------------------------------
extern "C" void kernel_launch(void* const* d_in, const int* in_sizes, int n_in,
                              void* d_out, int out_size)
{
    const float* src  = (const float*)d_in[0];
    const void*  mask_raw = d_in[1];
    const float* q_w = (const float*)d_in[2];
    const float* q_b = (const float*)d_in[3];
    const float* k_w = (const float*)d_in[4];
    const float* k_b = (const float*)d_in[5];
    const float* v_w = (const float*)d_in[6];
    const float* v_b = (const float*)d_in[7];
    const float* o_w = (const float*)d_in[8];
    const float* o_b = (const float*)d_in[9];
    const float* l1_w = (const float*)d_in[10];
    const float* l1_b = (const float*)d_in[11];
    const float* l2_w = (const float*)d_in[12];
    const float* l2_b = (const float*)d_in[13];
    const float* n1_s = (const float*)d_in[14];
    const float* n1_b = (const float*)d_in[15];
    const float* n2_s = (const float*)d_in[16];
    const float* n2_b = (const float*)d_in[17];
    const float* alpha_attn = (const float*)d_in[18];
    const float* alpha_ff   = (const float*)d_in[19];

    float *y, *x;
    unsigned char* maskc;
    __nv_bfloat16 *qB, *kB, *vB;
    __nv_bfloat16 *actH, *actL, *xH, *xL, *hH, *hL;
    __nv_bfloat16 *qwH, *qwL, *kwH, *kwL, *vwH, *vwL, *owH, *owL, *l1H, *l1L, *l2H, *l2L;
    cudaGetSymbolAddress((void**)&qB,   g_q);
    cudaGetSymbolAddress((void**)&kB,   g_k);
    cudaGetSymbolAddress((void**)&vB,   g_v);
    cudaGetSymbolAddress((void**)&y,    g_y);
    cudaGetSymbolAddress((void**)&x,    g_x);
    cudaGetSymbolAddress((void**)&maskc, g_mask);
    cudaGetSymbolAddress((void**)&actH, g_actH);
    cudaGetSymbolAddress((void**)&actL, g_actL);
    cudaGetSymbolAddress((void**)&xH,   g_xH);
    cudaGetSymbolAddress((void**)&xL,   g_xL);
    cudaGetSymbolAddress((void**)&hH,   g_hH);
    cudaGetSymbolAddress((void**)&hL,   g_hL);
    cudaGetSymbolAddress((void**)&qwH,  g_qwH);
    cudaGetSymbolAddress((void**)&qwL,  g_qwL);
    cudaGetSymbolAddress((void**)&kwH,  g_kwH);
    cudaGetSymbolAddress((void**)&kwL,  g_kwL);
    cudaGetSymbolAddress((void**)&vwH,  g_vwH);
    cudaGetSymbolAddress((void**)&vwL,  g_vwL);
    cudaGetSymbolAddress((void**)&owH,  g_owH);
    cudaGetSymbolAddress((void**)&owL,  g_owL);
    cudaGetSymbolAddress((void**)&l1H,  g_l1H);
    cudaGetSymbolAddress((void**)&l1L,  g_l1L);
    cudaGetSymbolAddress((void**)&l2H,  g_l2H);
    cudaGetSymbolAddress((void**)&l2L,  g_l2L);

    cudaFuncSetAttribute(gemm_mma<2>, cudaFuncAttributeMaxDynamicSharedMemorySize, GSM_DYN);
    cudaFuncSetAttribute(gemm_mma<3>, cudaFuncAttributeMaxDynamicSharedMemorySize, GSM_DYN);
    cudaFuncSetAttribute(gemm_mma<4>, cudaFuncAttributeMaxDynamicSharedMemorySize, GSM_DYN);
    cudaFuncSetAttribute(flash_attn_tc, cudaFuncAttributeMaxDynamicSharedMemorySize, ATT_SMEM);

    dim3 blk(256);
    dim3 grid_qkv(DD/128, MM/128);    // (8, 32)
    dim3 grid_ff1(FF/128, MM/128);    // (32, 32)

    // Mask canonicalization
    mask_scan_kernel<<<1, 1024>>>((const uint32_t*)mask_raw);
    mask_convert_kernel<<<(TT*TT/4 + 255)/256, 256>>>(mask_raw);

    // Weight + src splits
    split_kernel<<<(DD*DD/4 + 255)/256, 256>>>(q_w, qwH, qwL, DD*DD/4);
    split_kernel<<<(DD*DD/4 + 255)/256, 256>>>(k_w, kwH, kwL, DD*DD/4);
    split_kernel<<<(DD*DD/4 + 255)/256, 256>>>(v_w, vwH, vwL, DD*DD/4);
    split_kernel<<<(DD*DD/4 + 255)/256, 256>>>(o_w, owH, owL, DD*DD/4);
    split_kernel<<<(FF*DD/4 + 255)/256, 256>>>(l1_w, l1H, l1L, FF*DD/4);
    split_kernel<<<(DD*FF/4 + 255)/256, 256>>>(l2_w, l2H, l2L, DD*FF/4);
    split_kernel<<<(MM*DD/4 + 255)/256, 256>>>(src, actH, actL, MM*DD/4);

    // QKV projections -> plain bf16
    gemm_mma<3><<<grid_qkv, blk, GSM_DYN>>>(actH, actL, qwH, qwL, q_b, nullptr, MM, DD, DD, nullptr, nullptr, qB, nullptr);
    gemm_mma<3><<<grid_qkv, blk, GSM_DYN>>>(actH, actL, kwH, kwL, k_b, nullptr, MM, DD, DD, nullptr, nullptr, kB, nullptr);
    gemm_mma<3><<<grid_qkv, blk, GSM_DYN>>>(actH, actL, vwH, vwL, v_b, nullptr, MM, DD, DD, nullptr, nullptr, vB, nullptr);

    // Flash attention (writes split bf16 into actH/actL)
    flash_attn_tc<<<dim3(TT/128, HH, BB), blk, ATT_SMEM>>>(qB, kB, vB, maskc, actH, actL);

    // O projection + residual, LN1 (emits split of x)
    gemm_mma<2><<<grid_qkv, blk, GSM_DYN>>>(actH, actL, owH, owL, o_b, y, MM, DD, DD, src, alpha_attn, nullptr, nullptr);
    ln_kernel<1><<<MM, 256>>>(y, n1_s, n1_b, x, xH, xL);

    // FFN
    gemm_mma<4><<<grid_ff1, blk, GSM_DYN>>>(xH, xL, l1H, l1L, l1_b, nullptr, MM, FF, DD, nullptr, nullptr, hH, hL);
    gemm_mma<2><<<grid_qkv, blk, GSM_DYN>>>(hH, hL, l2H, l2L, l2_b, y, MM, DD, FF, x, alpha_ff, nullptr, nullptr);
    ln_kernel<0><<<MM, 256>>>(y, n2_s, n2_b, (float*)d_out, nullptr, nullptr);
}

// round 10
// speedup vs baseline: 4.4241x; 1.3296x over previous
#include <cuda_runtime.h>
#include <cuda_bf16.h>
#include <math.h>
#include <stdint.h>

// Problem constants
#define BB 2
#define TT 2048
#define DD 1024
#define HH 16
#define DHH 64
#define FF 4096
#define MM (BB*TT)          // 4096 rows

// ---------------------------------------------------------------------------
// Baseline-PTX tensor helpers (sm_80-era: mma.sync / ldmatrix / cp.async)
// ---------------------------------------------------------------------------
__device__ __forceinline__ uint32_t smem_u32(const void* p) {
    uint32_t a;
    asm("{ .reg .u64 t; cvta.to.shared.u64 t, %1; cvt.u32.u64 %0, t; }" : "=r"(a) : "l"(p));
    return a;
}
__device__ __forceinline__ void cpa16(uint32_t dst, const void* src) {
    asm volatile("cp.async.cg.shared.global [%0], [%1], 16;" :: "r"(dst), "l"(src) : "memory");
}
#define CP_COMMIT() asm volatile("cp.async.commit_group;" ::: "memory")
#define CP_WAIT0()  asm volatile("cp.async.wait_group 0;" ::: "memory")
#define CP_WAIT1()  asm volatile("cp.async.wait_group 1;" ::: "memory")

#define LDM4(r, a) \
    asm volatile("ldmatrix.sync.aligned.m8n8.x4.shared.b16 {%0,%1,%2,%3}, [%4];" \
        : "=r"((r)[0]), "=r"((r)[1]), "=r"((r)[2]), "=r"((r)[3]) : "r"(a))
#define LDM4T(r, a) \
    asm volatile("ldmatrix.sync.aligned.m8n8.x4.trans.shared.b16 {%0,%1,%2,%3}, [%4];" \
        : "=r"((r)[0]), "=r"((r)[1]), "=r"((r)[2]), "=r"((r)[3]) : "r"(a))

__device__ __forceinline__ void mma16816(float* d, const uint32_t* a, const uint32_t* b) {
    asm volatile("mma.sync.aligned.m16n8k16.row.col.f32.bf16.bf16.f32 "
        "{%0,%1,%2,%3}, {%4,%5,%6,%7}, {%8,%9}, {%0,%1,%2,%3};"
        : "+f"(d[0]), "+f"(d[1]), "+f"(d[2]), "+f"(d[3])
        : "r"(a[0]), "r"(a[1]), "r"(a[2]), "r"(a[3]), "r"(b[0]), "r"(b[1]));
}

// pack {lo, hi} floats into bf16x2 register (lo -> low half)
__device__ __forceinline__ uint32_t pkbf(float lo, float hi) {
    uint32_t d;
    asm("cvt.rn.bf16x2.f32 %0, %1, %2;" : "=r"(d) : "f"(hi), "f"(lo));
    return d;
}

// ---------------------------------------------------------------------------
// Scratch (allocation-free: __device__ globals)
// ---------------------------------------------------------------------------
__device__ float g_q[MM*DD];        // reused as bf16 q buffer
__device__ float g_k[MM*DD];        // reused as bf16 k buffer
__device__ float g_v[MM*DD];        // reused as bf16 v buffer
__device__ float g_y[MM*DD];
__device__ float g_x[MM*DD];
__device__ unsigned char g_mask[TT*TT];
__device__ int g_mask_mode;

// bf16 buffers
__device__ __nv_bfloat16 g_srcB[MM*DD];                  // src as bf16
__device__ __nv_bfloat16 g_attnB[MM*DD];                 // attention output bf16
__device__ __nv_bfloat16 g_xH[MM*DD],    g_xL[MM*DD];
__device__ __nv_bfloat16 g_hH[MM*FF],    g_hL[MM*FF];
__device__ __nv_bfloat16 g_qwH[DD*DD];
__device__ __nv_bfloat16 g_kwH[DD*DD];
__device__ __nv_bfloat16 g_vwH[DD*DD];
__device__ __nv_bfloat16 g_owH[DD*DD];
__device__ __nv_bfloat16 g_l1H[FF*DD],   g_l1L[FF*DD];
__device__ __nv_bfloat16 g_l2H[DD*FF],   g_l2L[DD*FF];

// ---------------------------------------------------------------------------
// fp32 -> (hi, lo) bf16 split, and plain fp32 -> bf16 convert
// ---------------------------------------------------------------------------
__global__ __launch_bounds__(256)
void split_kernel(const float* __restrict__ x, __nv_bfloat16* __restrict__ hi,
                  __nv_bfloat16* __restrict__ lo, int n4)
{
    int i = blockIdx.x * 256 + threadIdx.x;
    if (i >= n4) return;
    float4 v = ((const float4*)x)[i];
    float h0 = __bfloat162float(__float2bfloat16(v.x));
    float h1 = __bfloat162float(__float2bfloat16(v.y));
    float h2 = __bfloat162float(__float2bfloat16(v.z));
    float h3 = __bfloat162float(__float2bfloat16(v.w));
    uint2 hv = make_uint2(pkbf(h0, h1), pkbf(h2, h3));
    uint2 lv = make_uint2(pkbf(v.x - h0, v.y - h1), pkbf(v.z - h2, v.w - h3));
    ((uint2*)hi)[i] = hv;
    ((uint2*)lo)[i] = lv;
}

__global__ __launch_bounds__(256)
void tobf16_kernel(const float* __restrict__ x, __nv_bfloat16* __restrict__ out, int n4)
{
    int i = blockIdx.x * 256 + threadIdx.x;
    if (i >= n4) return;
    float4 v = ((const float4*)x)[i];
    ((uint2*)out)[i] = make_uint2(pkbf(v.x, v.y), pkbf(v.z, v.w));
}

// ---------------------------------------------------------------------------
// Mask dtype detection (prefix scan — statistically conclusive) + convert
// ---------------------------------------------------------------------------
__global__ __launch_bounds__(1024)
void mask_scan_kernel(const uint32_t* __restrict__ m)
{
    const int tid = threadIdx.x;
    int u8f = 0, f32f = 0;
    const int NW = 65536;   // 256KB prefix; buffer is >= 4MB in every mode
    for (int i = tid; i < NW; i += 1024) {
        uint32_t w = m[i];
        if (w != 0u && w != 1u && w != 0x3F800000u) u8f = 1;
        if (w == 0x3F800000u) f32f = 1;
    }
    __shared__ int s_u8, s_f32;
    if (tid == 0) { s_u8 = 0; s_f32 = 0; }
    __syncthreads();
    if (u8f)  atomicOr(&s_u8, 1);
    if (f32f) atomicOr(&s_f32, 1);
    __syncthreads();
    if (tid == 0)
        g_mask_mode = s_u8 ? 0 : (s_f32 ? 2 : 1);
}

__global__ __launch_bounds__(256)
void mask_convert_kernel(const void* __restrict__ min)
{
    const int mode = g_mask_mode;
    int i = blockIdx.x * blockDim.x + threadIdx.x;
    const int NW = (TT*TT) / 4;
    if (i >= NW) return;
    uint32_t out;
    if (mode == 0) {
        out = ((const uint32_t*)min)[i];
    } else if (mode == 1) {
        const int* p = (const int*)min;
        out  = (uint32_t)(p[4*i+0] != 0);
        out |= (uint32_t)(p[4*i+1] != 0) << 8;
        out |= (uint32_t)(p[4*i+2] != 0) << 16;
        out |= (uint32_t)(p[4*i+3] != 0) << 24;
    } else {
        const float* p = (const float*)min;
        out  = (uint32_t)(p[4*i+0] != 0.f);
        out |= (uint32_t)(p[4*i+1] != 0.f) << 8;
        out |= (uint32_t)(p[4*i+2] != 0.f) << 16;
        out |= (uint32_t)(p[4*i+3] != 0.f) << 24;
    }
    ((uint32_t*)g_mask)[i] = out;
}

// ---------------------------------------------------------------------------
// 3-term bf16-split GEMM (FFN): acc = Ah*Bh + Ah*Bl + Al*Bh
// EPI: 2 = res + alpha*(acc+bias) -> f32 C
//      4 = bias+relu -> split bf16 (outH, outL)
// ---------------------------------------------------------------------------
#define TILE_B   16384                 // 128 rows x 128 bytes (64 bf16)
#define STAGE_B  (4*TILE_B)            // Ah, Al, Bh, Bl
#define GSM_DYN  (2*STAGE_B + 1024)

template<int EPI>
__global__ __launch_bounds__(256, 1)
void gemm_mma(const __nv_bfloat16* __restrict__ Ah, const __nv_bfloat16* __restrict__ Al,
              const __nv_bfloat16* __restrict__ Bh, const __nv_bfloat16* __restrict__ Bl,
              const float* __restrict__ bias, float* __restrict__ C,
              int M, int N, int K,
              const float* __restrict__ res, const float* __restrict__ alpha_p,
              __nv_bfloat16* __restrict__ outH, __nv_bfloat16* __restrict__ outL)
{
    extern __shared__ unsigned char sm[];
    const uint32_t smu  = smem_u32(sm);
    const uint32_t base = (smu + 1023) & ~1023u;

    const int tid  = threadIdx.x;
    const int wid  = tid >> 5;
    const int lane = tid & 31;
    const int wm   = wid >> 2;
    const int wn   = wid & 3;
    const int bm   = blockIdx.y * 128;
    const int bn   = blockIdx.x * 128;

    float d[4][4][4];
    #pragma unroll
    for (int i = 0; i < 4; i++)
        #pragma unroll
        for (int j = 0; j < 4; j++)
            #pragma unroll
            for (int q = 0; q < 4; q++) d[i][j][q] = 0.f;

    const int srow = tid >> 1;
    const int sc0  = (tid & 1) * 4;
    const uint32_t swrowbase = (uint32_t)srow * 128;
    const int rx = srow & 7;

    const int NC = K >> 6;

    {
        const uint32_t st = base;
        #pragma unroll
        for (int j = 0; j < 4; j++) {
            const int c = sc0 + j;
            const uint32_t sw = swrowbase + ((uint32_t)(c ^ rx) << 4);
            const size_t goA = (size_t)(bm + srow) * K + c * 8;
            const size_t goB = (size_t)(bn + srow) * K + c * 8;
            cpa16(st + 0*TILE_B + sw, Ah + goA);
            cpa16(st + 1*TILE_B + sw, Al + goA);
            cpa16(st + 2*TILE_B + sw, Bh + goB);
            cpa16(st + 3*TILE_B + sw, Bl + goB);
        }
        CP_COMMIT();
    }

    for (int ch = 0; ch < NC; ch++) {
        CP_WAIT0();
        __syncthreads();

        if (ch + 1 < NC) {
            const uint32_t st = base + ((ch + 1) & 1) * STAGE_B;
            const size_t k0 = (size_t)(ch + 1) * 64;
            #pragma unroll
            for (int j = 0; j < 4; j++) {
                const int c = sc0 + j;
                const uint32_t sw = swrowbase + ((uint32_t)(c ^ rx) << 4);
                const size_t goA = (size_t)(bm + srow) * K + k0 + c * 8;
                const size_t goB = (size_t)(bn + srow) * K + k0 + c * 8;
                cpa16(st + 0*TILE_B + sw, Ah + goA);
                cpa16(st + 1*TILE_B + sw, Al + goA);
                cpa16(st + 2*TILE_B + sw, Bh + goB);
                cpa16(st + 3*TILE_B + sw, Bl + goB);
            }
            CP_COMMIT();
        }

        const uint32_t st = base + (ch & 1) * STAGE_B;
        const uint32_t aHs = st, aLs = st + TILE_B, bHs = st + 2*TILE_B, bLs = st + 3*TILE_B;

        const int arow_base = wm * 64 + (lane & 15);
        const int akh = lane >> 4;
        const int brow_base = wn * 32 + (lane & 7) + ((lane >> 4) << 3);
        const int bkh = (lane >> 3) & 1;

        #pragma unroll
        for (int k16 = 0; k16 < 4; k16++) {
            uint32_t ah[4][4], al[4][4], bh[2][4], bl[2][4];
            #pragma unroll
            for (int mt = 0; mt < 4; mt++) {
                const int row = arow_base + mt * 16;
                const uint32_t cb = (uint32_t)(k16 * 32 + akh * 16);
                const uint32_t off = (uint32_t)row * 128 + (cb ^ ((uint32_t)(row & 7) << 4));
                LDM4(ah[mt], aHs + off);
                LDM4(al[mt], aLs + off);
            }
            #pragma unroll
            for (int bt = 0; bt < 2; bt++) {
                const int row = brow_base + bt * 16;
                const uint32_t cb = (uint32_t)(k16 * 32 + bkh * 16);
                const uint32_t off = (uint32_t)row * 128 + (cb ^ ((uint32_t)(row & 7) << 4));
                LDM4(bh[bt], bHs + off);
                LDM4(bl[bt], bLs + off);
            }
            #pragma unroll
            for (int mt = 0; mt < 4; mt++) {
                #pragma unroll
                for (int nt = 0; nt < 4; nt++) {
                    const uint32_t* bhp = &bh[nt >> 1][(nt & 1) * 2];
                    const uint32_t* blp = &bl[nt >> 1][(nt & 1) * 2];
                    mma16816(d[mt][nt], ah[mt], bhp);
                    mma16816(d[mt][nt], ah[mt], blp);
                    mma16816(d[mt][nt], al[mt], bhp);
                }
            }
        }
        __syncthreads();
    }

    float alpha = 0.f;
    if (EPI == 2) alpha = *alpha_p;
    const int g  = lane >> 2;
    const int nq = (lane & 3) * 2;

    #pragma unroll
    for (int mt = 0; mt < 4; mt++) {
        const int m0 = bm + wm * 64 + mt * 16 + g;
        #pragma unroll
        for (int nt = 0; nt < 4; nt++) {
            const int n = bn + wn * 32 + nt * 8 + nq;
            float2 b2 = *(const float2*)&bias[n];
            float2 o0 = make_float2(d[mt][nt][0] + b2.x, d[mt][nt][1] + b2.y);
            float2 o1 = make_float2(d[mt][nt][2] + b2.x, d[mt][nt][3] + b2.y);
            if (EPI == 4) {
                o0.x = fmaxf(o0.x, 0.f); o0.y = fmaxf(o0.y, 0.f);
                o1.x = fmaxf(o1.x, 0.f); o1.y = fmaxf(o1.y, 0.f);
            }
            if (EPI == 2) {
                float2 r0 = *(const float2*)&res[(size_t)m0 * N + n];
                float2 r1 = *(const float2*)&res[(size_t)(m0 + 8) * N + n];
                o0.x = r0.x + alpha * o0.x; o0.y = r0.y + alpha * o0.y;
                o1.x = r1.x + alpha * o1.x; o1.y = r1.y + alpha * o1.y;
                *(float2*)&C[(size_t)m0 * N + n]       = o0;
                *(float2*)&C[(size_t)(m0 + 8) * N + n] = o1;
            } else {
                float h0 = __bfloat162float(__float2bfloat16(o0.x));
                float h1 = __bfloat162float(__float2bfloat16(o0.y));
                float h2 = __bfloat162float(__float2bfloat16(o1.x));
                float h3 = __bfloat162float(__float2bfloat16(o1.y));
                *(uint32_t*)&outH[(size_t)m0 * N + n]       = pkbf(h0, h1);
                *(uint32_t*)&outH[(size_t)(m0 + 8) * N + n] = pkbf(h2, h3);
                *(uint32_t*)&outL[(size_t)m0 * N + n]       = pkbf(o0.x - h0, o0.y - h1);
                *(uint32_t*)&outL[(size_t)(m0 + 8) * N + n] = pkbf(o1.x - h2, o1.y - h3);
            }
        }
    }
}

// ---------------------------------------------------------------------------
// 1-term plain bf16 GEMM (QKV, O-proj): acc = A*B
// EPI: 2 = res + alpha*(acc+bias) -> f32 C
//      3 = bias -> bf16 out
// 64KB smem (2 stages x 2 tiles) -> 2 CTAs/SM.
// ---------------------------------------------------------------------------
#define BSTAGE_B (2*TILE_B)
#define GBF_DYN  (2*BSTAGE_B + 1024)

template<int EPI>
__global__ __launch_bounds__(256, 2)
void gemm_bf(const __nv_bfloat16* __restrict__ A, const __nv_bfloat16* __restrict__ B,
             const float* __restrict__ bias, float* __restrict__ C,
             int M, int N, int K,
             const float* __restrict__ res, const float* __restrict__ alpha_p,
             __nv_bfloat16* __restrict__ out)
{
    extern __shared__ unsigned char sm[];
    const uint32_t smu  = smem_u32(sm);
    const uint32_t base = (smu + 1023) & ~1023u;

    const int tid  = threadIdx.x;
    const int wid  = tid >> 5;
    const int lane = tid & 31;
    const int wm   = wid >> 2;
    const int wn   = wid & 3;
    const int bm   = blockIdx.y * 128;
    const int bn   = blockIdx.x * 128;

    float d[4][4][4];
    #pragma unroll
    for (int i = 0; i < 4; i++)
        #pragma unroll
        for (int j = 0; j < 4; j++)
            #pragma unroll
            for (int q = 0; q < 4; q++) d[i][j][q] = 0.f;

    const int srow = tid >> 1;
    const int sc0  = (tid & 1) * 4;
    const uint32_t swrowbase = (uint32_t)srow * 128;
    const int rx = srow & 7;

    const int NC = K >> 6;

    {
        const uint32_t st = base;
        #pragma unroll
        for (int j = 0; j < 4; j++) {
            const int c = sc0 + j;
            const uint32_t sw = swrowbase + ((uint32_t)(c ^ rx) << 4);
            cpa16(st + sw,          A + (size_t)(bm + srow) * K + c * 8);
            cpa16(st + TILE_B + sw, B + (size_t)(bn + srow) * K + c * 8);
        }
        CP_COMMIT();
    }

    for (int ch = 0; ch < NC; ch++) {
        CP_WAIT0();
        __syncthreads();

        if (ch + 1 < NC) {
            const uint32_t st = base + ((ch + 1) & 1) * BSTAGE_B;
            const size_t k0 = (size_t)(ch + 1) * 64;
            #pragma unroll
            for (int j = 0; j < 4; j++) {
                const int c = sc0 + j;
                const uint32_t sw = swrowbase + ((uint32_t)(c ^ rx) << 4);
                cpa16(st + sw,          A + (size_t)(bm + srow) * K + k0 + c * 8);
                cpa16(st + TILE_B + sw, B + (size_t)(bn + srow) * K + k0 + c * 8);
            }
            CP_COMMIT();
        }

        const uint32_t st = base + (ch & 1) * BSTAGE_B;
        const uint32_t aS = st, bS = st + TILE_B;

        const int arow_base = wm * 64 + (lane & 15);
        const int akh = lane >> 4;
        const int brow_base = wn * 32 + (lane & 7) + ((lane >> 4) << 3);
        const int bkh = (lane >> 3) & 1;

        #pragma unroll
        for (int k16 = 0; k16 < 4; k16++) {
            uint32_t a[4][4], b[2][4];
            #pragma unroll
            for (int mt = 0; mt < 4; mt++) {
                const int row = arow_base + mt * 16;
                const uint32_t cb = (uint32_t)(k16 * 32 + akh * 16);
                LDM4(a[mt], aS + (uint32_t)row * 128 + (cb ^ ((uint32_t)(row & 7) << 4)));
            }
            #pragma unroll
            for (int bt = 0; bt < 2; bt++) {
                const int row = brow_base + bt * 16;
                const uint32_t cb = (uint32_t)(k16 * 32 + bkh * 16);
                LDM4(b[bt], bS + (uint32_t)row * 128 + (cb ^ ((uint32_t)(row & 7) << 4)));
            }
            #pragma unroll
            for (int mt = 0; mt < 4; mt++)
                #pragma unroll
                for (int nt = 0; nt < 4; nt++)
                    mma16816(d[mt][nt], a[mt], &b[nt >> 1][(nt & 1) * 2]);
        }
        __syncthreads();
    }

    float alpha = 0.f;
    if (EPI == 2) alpha = *alpha_p;
    const int g  = lane >> 2;
    const int nq = (lane & 3) * 2;

    #pragma unroll
    for (int mt = 0; mt < 4; mt++) {
        const int m0 = bm + wm * 64 + mt * 16 + g;
        #pragma unroll
        for (int nt = 0; nt < 4; nt++) {
            const int n = bn + wn * 32 + nt * 8 + nq;
            float2 b2 = *(const float2*)&bias[n];
            float2 o0 = make_float2(d[mt][nt][0] + b2.x, d[mt][nt][1] + b2.y);
            float2 o1 = make_float2(d[mt][nt][2] + b2.x, d[mt][nt][3] + b2.y);
            if (EPI == 2) {
                float2 r0 = *(const float2*)&res[(size_t)m0 * N + n];
                float2 r1 = *(const float2*)&res[(size_t)(m0 + 8) * N + n];
                o0.x = r0.x + alpha * o0.x; o0.y = r0.y + alpha * o0.y;
                o1.x = r1.x + alpha * o1.x; o1.y = r1.y + alpha * o1.y;
                *(float2*)&C[(size_t)m0 * N + n]       = o0;
                *(float2*)&C[(size_t)(m0 + 8) * N + n] = o1;
            } else {
                *(uint32_t*)&out[(size_t)m0 * N + n]       = pkbf(o0.x, o0.y);
                *(uint32_t*)&out[(size_t)(m0 + 8) * N + n] = pkbf(o1.x, o1.y);
            }
        }
    }
}

// ---------------------------------------------------------------------------
// Tensor-core flash attention (bf16 mma, fp32 softmax). Plain bf16 output.
// ---------------------------------------------------------------------------
#define MPAD 80
#define KV_B  8192
#define MB_B  (128*MPAD)
#define BUF_B (2*KV_B + MB_B)
#define ATT_SMEM (16384 + 2*BUF_B + 1024)

__global__ __launch_bounds__(256, 2)
void flash_attn_tc(const __nv_bfloat16* __restrict__ Qb, const __nv_bfloat16* __restrict__ Kb,
                   const __nv_bfloat16* __restrict__ Vb, const unsigned char* __restrict__ mask,
                   __nv_bfloat16* __restrict__ OH)
{
    extern __shared__ unsigned char sm[];
    const uint32_t smu = smem_u32(sm);
    const uint32_t Qs  = (smu + 1023) & ~1023u;

    const int tid = threadIdx.x, wid = tid >> 5, lane = tid & 31;
    const int q0 = blockIdx.x * 128;
    const int h  = blockIdx.y, b = blockIdx.z;
    const size_t rowbase = (size_t)b * TT;
    const int colh = h * DHH;

    {
        const int r = tid >> 1, c0 = (tid & 1) * 4;
        const __nv_bfloat16* src = Qb + (rowbase + q0 + r) * DD + colh;
        #pragma unroll
        for (int j = 0; j < 4; j++) {
            const int c = c0 + j;
            cpa16(Qs + r * 128 + ((uint32_t)(c ^ (r & 7)) << 4), src + c * 8);
        }
    }
    {
        const uint32_t Ks = Qs + 16384, Vs = Ks + KV_B, Ms = Vs + KV_B;
        const int r = tid >> 2;
        const int j2 = tid & 3;
        #pragma unroll
        for (int j = 0; j < 2; j++) {
            const int c = j2 * 2 + j;
            const uint32_t sw = r * 128 + ((uint32_t)(c ^ (r & 7)) << 4);
            cpa16(Ks + sw, Kb + (rowbase + r) * DD + colh + c * 8);
            cpa16(Vs + sw, Vb + (rowbase + r) * DD + colh + c * 8);
        }
        const int mr = tid >> 1;
        #pragma unroll
        for (int j = 0; j < 2; j++) {
            const int c = (tid & 1) * 2 + j;
            cpa16(Ms + mr * MPAD + c * 16, mask + (size_t)(q0 + mr) * TT + c * 16);
        }
        CP_COMMIT();
    }

    float m0 = -1e30f, m1 = -1e30f, l0 = 0.f, l1 = 0.f;
    float o[8][4];
    #pragma unroll
    for (int i = 0; i < 8; i++)
        #pragma unroll
        for (int j = 0; j < 4; j++) o[i][j] = 0.f;

    uint32_t aQ[4][4];
    const int arow = wid * 16 + (lane & 15);
    const int akh  = lane >> 4;
    const int brow = (lane & 7) + ((lane >> 4) << 3);
    const int bkh  = (lane >> 3) & 1;
    const int r0   = lane >> 2;
    const int cq   = (lane & 3) * 2;

    const int NT = TT / 64;
    for (int st = 0; st < NT; st++) {
        if (st + 1 < NT) {
            const uint32_t base = Qs + 16384 + ((st + 1) & 1) * BUF_B;
            const uint32_t Ks = base, Vs = base + KV_B, Ms = base + 2*KV_B;
            const int s1 = (st + 1) * 64;
            const int r = tid >> 2, j2 = tid & 3;
            #pragma unroll
            for (int j = 0; j < 2; j++) {
                const int c = j2 * 2 + j;
                const uint32_t sw = r * 128 + ((uint32_t)(c ^ (r & 7)) << 4);
                cpa16(Ks + sw, Kb + (rowbase + s1 + r) * DD + colh + c * 8);
                cpa16(Vs + sw, Vb + (rowbase + s1 + r) * DD + colh + c * 8);
            }
            const int mr = tid >> 1;
            #pragma unroll
            for (int j = 0; j < 2; j++) {
                const int c = (tid & 1) * 2 + j;
                cpa16(Ms + mr * MPAD + c * 16, mask + (size_t)(q0 + mr) * TT + s1 + c * 16);
            }
            CP_COMMIT();
            CP_WAIT1();
        } else {
            CP_WAIT0();
        }
        __syncthreads();

        if (st == 0) {
            #pragma unroll
            for (int kt = 0; kt < 4; kt++) {
                const uint32_t cb = (uint32_t)(kt * 32 + akh * 16);
                LDM4(aQ[kt], Qs + (uint32_t)arow * 128 + (cb ^ ((uint32_t)(arow & 7) << 4)));
            }
        }

        const uint32_t base = Qs + 16384 + (st & 1) * BUF_B;
        const uint32_t Ks = base, Vs = base + KV_B, Ms = base + 2*KV_B;

        float sacc[8][4];
        #pragma unroll
        for (int i = 0; i < 8; i++)
            #pragma unroll
            for (int j = 0; j < 4; j++) sacc[i][j] = 0.f;

        #pragma unroll
        for (int kt = 0; kt < 4; kt++) {
            uint32_t bK[4][4];
            #pragma unroll
            for (int bt = 0; bt < 4; bt++) {
                const int row = brow + bt * 16;
                const uint32_t cb = (uint32_t)(kt * 32 + bkh * 16);
                LDM4(bK[bt], Ks + (uint32_t)row * 128 + (cb ^ ((uint32_t)(row & 7) << 4)));
            }
            #pragma unroll
            for (int nt = 0; nt < 8; nt++)
                mma16816(sacc[nt], aQ[kt], &bK[nt >> 1][(nt & 1) * 2]);
        }

        const int mrow0 = wid * 16 + r0;
        float mx0 = -1e30f, mx1 = -1e30f;
        #pragma unroll
        for (int nt = 0; nt < 8; nt++) {
            uchar2 k0 = *(const uchar2*)(sm + (Ms - smu) + mrow0 * MPAD + nt * 8 + cq);
            uchar2 k1 = *(const uchar2*)(sm + (Ms - smu) + (mrow0 + 8) * MPAD + nt * 8 + cq);
            sacc[nt][0] = k0.x ? -1e30f : sacc[nt][0] * 0.125f;
            sacc[nt][1] = k0.y ? -1e30f : sacc[nt][1] * 0.125f;
            sacc[nt][2] = k1.x ? -1e30f : sacc[nt][2] * 0.125f;
            sacc[nt][3] = k1.y ? -1e30f : sacc[nt][3] * 0.125f;
            mx0 = fmaxf(mx0, fmaxf(sacc[nt][0], sacc[nt][1]));
            mx1 = fmaxf(mx1, fmaxf(sacc[nt][2], sacc[nt][3]));
        }
        mx0 = fmaxf(mx0, __shfl_xor_sync(0xffffffffu, mx0, 1));
        mx0 = fmaxf(mx0, __shfl_xor_sync(0xffffffffu, mx0, 2));
        mx1 = fmaxf(mx1, __shfl_xor_sync(0xffffffffu, mx1, 1));
        mx1 = fmaxf(mx1, __shfl_xor_sync(0xffffffffu, mx1, 2));

        const float mn0 = fmaxf(m0, mx0), mn1 = fmaxf(m1, mx1);
        const float af0 = __expf(m0 - mn0), af1 = __expf(m1 - mn1);
        float rs0 = 0.f, rs1 = 0.f;
        #pragma unroll
        for (int nt = 0; nt < 8; nt++) {
            float p0 = (sacc[nt][0] == -1e30f) ? 0.f : __expf(sacc[nt][0] - mn0);
            float p1 = (sacc[nt][1] == -1e30f) ? 0.f : __expf(sacc[nt][1] - mn0);
            float p2 = (sacc[nt][2] == -1e30f) ? 0.f : __expf(sacc[nt][2] - mn1);
            float p3 = (sacc[nt][3] == -1e30f) ? 0.f : __expf(sacc[nt][3] - mn1);
            sacc[nt][0] = p0; sacc[nt][1] = p1; sacc[nt][2] = p2; sacc[nt][3] = p3;
            rs0 += p0 + p1; rs1 += p2 + p3;
        }
        rs0 += __shfl_xor_sync(0xffffffffu, rs0, 1);
        rs0 += __shfl_xor_sync(0xffffffffu, rs0, 2);
        rs1 += __shfl_xor_sync(0xffffffffu, rs1, 1);
        rs1 += __shfl_xor_sync(0xffffffffu, rs1, 2);
        l0 = af0 * l0 + rs0;  m0 = mn0;
        l1 = af1 * l1 + rs1;  m1 = mn1;

        #pragma unroll
        for (int nt = 0; nt < 8; nt++) {
            o[nt][0] *= af0; o[nt][1] *= af0;
            o[nt][2] *= af1; o[nt][3] *= af1;
        }

        uint32_t pf[4][4];
        #pragma unroll
        for (int kt = 0; kt < 4; kt++) {
            pf[kt][0] = pkbf(sacc[2*kt][0],   sacc[2*kt][1]);
            pf[kt][1] = pkbf(sacc[2*kt][2],   sacc[2*kt][3]);
            pf[kt][2] = pkbf(sacc[2*kt+1][0], sacc[2*kt+1][1]);
            pf[kt][3] = pkbf(sacc[2*kt+1][2], sacc[2*kt+1][3]);
        }

        #pragma unroll
        for (int kt = 0; kt < 4; kt++) {
            #pragma unroll
            for (int nt2 = 0; nt2 < 4; nt2++) {
                uint32_t bV[4];
                const int rv = kt * 16 + (lane & 15);
                const uint32_t c = (uint32_t)(nt2 * 2 + (lane >> 4));
                LDM4T(bV, Vs + (uint32_t)rv * 128 + ((c ^ (uint32_t)(rv & 7)) << 4));
                mma16816(o[2*nt2],     pf[kt], &bV[0]);
                mma16816(o[2*nt2 + 1], pf[kt], &bV[2]);
            }
        }
        __syncthreads();
    }

    const float inv0 = (l0 > 0.f) ? 1.f / l0 : 0.f;
    const float inv1 = (l1 > 0.f) ? 1.f / l1 : 0.f;
    const size_t row0 = rowbase + q0 + wid * 16 + r0;
    #pragma unroll
    for (int nt = 0; nt < 8; nt++) {
        const int n = colh + nt * 8 + cq;
        *(uint32_t*)&OH[row0 * DD + n]       = pkbf(o[nt][0] * inv0, o[nt][1] * inv0);
        *(uint32_t*)&OH[(row0 + 8) * DD + n] = pkbf(o[nt][2] * inv1, o[nt][3] * inv1);
    }
}

// ---------------------------------------------------------------------------
// Row LayerNorm; SPLIT=1 additionally emits bf16 hi/lo split of the output.
// ---------------------------------------------------------------------------
template<int SPLIT>
__global__ __launch_bounds__(256)
void ln_kernel(const float* __restrict__ Y, const float* __restrict__ sc,
               const float* __restrict__ bi, float* __restrict__ X,
               __nv_bfloat16* __restrict__ outH, __nv_bfloat16* __restrict__ outL)
{
    const int row = blockIdx.x;
    const int tid = threadIdx.x;
    const float4 v = ((const float4*)(Y + (size_t)row * DD))[tid];

    float s  = v.x + v.y + v.z + v.w;
    float ss = v.x*v.x + v.y*v.y + v.z*v.z + v.w*v.w;
    #pragma unroll
    for (int off = 16; off >= 1; off >>= 1) {
        s  += __shfl_xor_sync(0xffffffffu, s,  off);
        ss += __shfl_xor_sync(0xffffffffu, ss, off);
    }

    __shared__ float ws[8], wss[8];
    __shared__ float mean_sh, rstd_sh;
    if ((tid & 31) == 0) { ws[tid >> 5] = s; wss[tid >> 5] = ss; }
    __syncthreads();
    if (tid == 0) {
        float S = 0.f, SS = 0.f;
        #pragma unroll
        for (int k = 0; k < 8; k++) { S += ws[k]; SS += wss[k]; }
        float mu = S / (float)DD;
        float var = SS / (float)DD - mu * mu;
        mean_sh = mu;
        rstd_sh = rsqrtf(var + 1e-5f);
    }
    __syncthreads();
    const float mu = mean_sh, rs = rstd_sh;

    const float4 sc4 = ((const float4*)sc)[tid];
    const float4 b4  = ((const float4*)bi)[tid];
    float4 o;
    o.x = (v.x - mu) * rs * sc4.x + b4.x;
    o.y = (v.y - mu) * rs * sc4.y + b4.y;
    o.z = (v.z - mu) * rs * sc4.z + b4.z;
    o.w = (v.w - mu) * rs * sc4.w + b4.w;
    ((float4*)(X + (size_t)row * DD))[tid] = o;

    if (SPLIT) {
        float h0 = __bfloat162float(__float2bfloat16(o.x));
        float h1 = __bfloat162float(__float2bfloat16(o.y));
        float h2 = __bfloat162float(__float2bfloat16(o.z));
        float h3 = __bfloat162float(__float2bfloat16(o.w));
        uint2 hv = make_uint2(pkbf(h0, h1), pkbf(h2, h3));
        uint2 lv = make_uint2(pkbf(o.x - h0, o.y - h1), pkbf(o.z - h2, o.w - h3));
        *(uint2*)&outH[(size_t)row * DD + tid * 4] = hv;
        *(uint2*)&outL[(size_t)row * DD + tid * 4] = lv;
    }
}

// ---------------------------------------------------------------------------
// Launch
// ---------------------------------------------------------------------------
extern "C" void kernel_launch(void* const* d_in, const int* in_sizes, int n_in,
                              void* d_out, int out_size)
{
    const float* src  = (const float*)d_in[0];
    const void*  mask_raw = d_in[1];
    const float* q_w = (const float*)d_in[2];
    const float* q_b = (const float*)d_in[3];
    const float* k_w = (const float*)d_in[4];
    const float* k_b = (const float*)d_in[5];
    const float* v_w = (const float*)d_in[6];
    const float* v_b = (const float*)d_in[7];
    const float* o_w = (const float*)d_in[8];
    const float* o_b = (const float*)d_in[9];
    const float* l1_w = (const float*)d_in[10];
    const float* l1_b = (const float*)d_in[11];
    const float* l2_w = (const float*)d_in[12];
    const float* l2_b = (const float*)d_in[13];
    const float* n1_s = (const float*)d_in[14];
    const float* n1_b = (const float*)d_in[15];
    const float* n2_s = (const float*)d_in[16];
    const float* n2_b = (const float*)d_in[17];
    const float* alpha_attn = (const float*)d_in[18];
    const float* alpha_ff   = (const float*)d_in[19];

    float *y, *x;
    unsigned char* maskc;
    __nv_bfloat16 *qB, *kB, *vB, *srcB, *attnB;
    __nv_bfloat16 *xH, *xL, *hH, *hL;
    __nv_bfloat16 *qwH, *kwH, *vwH, *owH, *l1H, *l1L, *l2H, *l2L;
    cudaGetSymbolAddress((void**)&qB,   g_q);
    cudaGetSymbolAddress((void**)&kB,   g_k);
    cudaGetSymbolAddress((void**)&vB,   g_v);
    cudaGetSymbolAddress((void**)&y,    g_y);
    cudaGetSymbolAddress((void**)&x,    g_x);
    cudaGetSymbolAddress((void**)&maskc, g_mask);
    cudaGetSymbolAddress((void**)&srcB, g_srcB);
    cudaGetSymbolAddress((void**)&attnB, g_attnB);
    cudaGetSymbolAddress((void**)&xH,   g_xH);
    cudaGetSymbolAddress((void**)&xL,   g_xL);
    cudaGetSymbolAddress((void**)&hH,   g_hH);
    cudaGetSymbolAddress((void**)&hL,   g_hL);
    cudaGetSymbolAddress((void**)&qwH,  g_qwH);
    cudaGetSymbolAddress((void**)&kwH,  g_kwH);
    cudaGetSymbolAddress((void**)&vwH,  g_vwH);
    cudaGetSymbolAddress((void**)&owH,  g_owH);
    cudaGetSymbolAddress((void**)&l1H,  g_l1H);
    cudaGetSymbolAddress((void**)&l1L,  g_l1L);
    cudaGetSymbolAddress((void**)&l2H,  g_l2H);
    cudaGetSymbolAddress((void**)&l2L,  g_l2L);

    cudaFuncSetAttribute(gemm_mma<2>, cudaFuncAttributeMaxDynamicSharedMemorySize, GSM_DYN);
    cudaFuncSetAttribute(gemm_mma<4>, cudaFuncAttributeMaxDynamicSharedMemorySize, GSM_DYN);
    cudaFuncSetAttribute(gemm_bf<2>, cudaFuncAttributeMaxDynamicSharedMemorySize, GBF_DYN);
    cudaFuncSetAttribute(gemm_bf<3>, cudaFuncAttributeMaxDynamicSharedMemorySize, GBF_DYN);
    cudaFuncSetAttribute(flash_attn_tc, cudaFuncAttributeMaxDynamicSharedMemorySize, ATT_SMEM);

    dim3 blk(256);
    dim3 grid_qkv(DD/128, MM/128);    // (8, 32)
    dim3 grid_ff1(FF/128, MM/128);    // (32, 32)

    // Mask canonicalization
    mask_scan_kernel<<<1, 1024>>>((const uint32_t*)mask_raw);
    mask_convert_kernel<<<(TT*TT/4 + 255)/256, 256>>>(mask_raw);

    // Weight conversions: hi-only for QKV/O, split for FFN
    tobf16_kernel<<<(DD*DD/4 + 255)/256, 256>>>(q_w, qwH, DD*DD/4);
    tobf16_kernel<<<(DD*DD/4 + 255)/256, 256>>>(k_w, kwH, DD*DD/4);
    tobf16_kernel<<<(DD*DD/4 + 255)/256, 256>>>(v_w, vwH, DD*DD/4);
    tobf16_kernel<<<(DD*DD/4 + 255)/256, 256>>>(o_w, owH, DD*DD/4);
    split_kernel<<<(FF*DD/4 + 255)/256, 256>>>(l1_w, l1H, l1L, FF*DD/4);
    split_kernel<<<(DD*FF/4 + 255)/256, 256>>>(l2_w, l2H, l2L, DD*FF/4);
    tobf16_kernel<<<(MM*DD/4 + 255)/256, 256>>>(src, srcB, MM*DD/4);

    // QKV projections (1-term bf16) -> bf16 q/k/v
    gemm_bf<3><<<grid_qkv, blk, GBF_DYN>>>(srcB, qwH, q_b, nullptr, MM, DD, DD, nullptr, nullptr, qB);
    gemm_bf<3><<<grid_qkv, blk, GBF_DYN>>>(srcB, kwH, k_b, nullptr, MM, DD, DD, nullptr, nullptr, kB);
    gemm_bf<3><<<grid_qkv, blk, GBF_DYN>>>(srcB, vwH, v_b, nullptr, MM, DD, DD, nullptr, nullptr, vB);

    // Flash attention -> plain bf16
    flash_attn_tc<<<dim3(TT/128, HH, BB), blk, ATT_SMEM>>>(qB, kB, vB, maskc, attnB);

    // O projection (1-term) + residual, LN1 (emits split of x)
    gemm_bf<2><<<grid_qkv, blk, GBF_DYN>>>(attnB, owH, o_b, y, MM, DD, DD, src, alpha_attn, nullptr);
    ln_kernel<1><<<MM, 256>>>(y, n1_s, n1_b, x, xH, xL);

    // FFN (3-term split)
    gemm_mma<4><<<grid_ff1, blk, GSM_DYN>>>(xH, xL, l1H, l1L, l1_b, nullptr, MM, FF, DD, nullptr, nullptr, hH, hL);
    gemm_mma<2><<<grid_qkv, blk, GSM_DYN>>>(hH, hL, l2H, l2L, l2_b, y, MM, DD, FF, x, alpha_ff, nullptr, nullptr);
    ln_kernel<0><<<MM, 256>>>(y, n2_s, n2_b, (float*)d_out, nullptr, nullptr);
}

// round 11
// speedup vs baseline: 7.2577x; 1.6405x over previous
#include <cuda_runtime.h>
#include <cuda_bf16.h>
#include <cuda_fp16.h>
#include <math.h>
#include <stdint.h>

// Problem constants
#define BB 2
#define TT 2048
#define DD 1024
#define HH 16
#define DHH 64
#define FF 4096
#define MM (BB*TT)          // 4096 rows

// ---------------------------------------------------------------------------
// Baseline-PTX tensor helpers (sm_80-era: mma.sync / ldmatrix / cp.async)
// ---------------------------------------------------------------------------
__device__ __forceinline__ uint32_t smem_u32(const void* p) {
    uint32_t a;
    asm("{ .reg .u64 t; cvta.to.shared.u64 t, %1; cvt.u32.u64 %0, t; }" : "=r"(a) : "l"(p));
    return a;
}
__device__ __forceinline__ void cpa16(uint32_t dst, const void* src) {
    asm volatile("cp.async.cg.shared.global [%0], [%1], 16;" :: "r"(dst), "l"(src) : "memory");
}
#define CP_COMMIT() asm volatile("cp.async.commit_group;" ::: "memory")
#define CP_WAIT0()  asm volatile("cp.async.wait_group 0;" ::: "memory")
#define CP_WAIT1()  asm volatile("cp.async.wait_group 1;" ::: "memory")

#define LDM4(r, a) \
    asm volatile("ldmatrix.sync.aligned.m8n8.x4.shared.b16 {%0,%1,%2,%3}, [%4];" \
        : "=r"((r)[0]), "=r"((r)[1]), "=r"((r)[2]), "=r"((r)[3]) : "r"(a))
#define LDM4T(r, a) \
    asm volatile("ldmatrix.sync.aligned.m8n8.x4.trans.shared.b16 {%0,%1,%2,%3}, [%4];" \
        : "=r"((r)[0]), "=r"((r)[1]), "=r"((r)[2]), "=r"((r)[3]) : "r"(a))

__device__ __forceinline__ void mma_bf16(float* d, const uint32_t* a, const uint32_t* b) {
    asm volatile("mma.sync.aligned.m16n8k16.row.col.f32.bf16.bf16.f32 "
        "{%0,%1,%2,%3}, {%4,%5,%6,%7}, {%8,%9}, {%0,%1,%2,%3};"
        : "+f"(d[0]), "+f"(d[1]), "+f"(d[2]), "+f"(d[3])
        : "r"(a[0]), "r"(a[1]), "r"(a[2]), "r"(a[3]), "r"(b[0]), "r"(b[1]));
}
__device__ __forceinline__ void mma_fp16(float* d, const uint32_t* a, const uint32_t* b) {
    asm volatile("mma.sync.aligned.m16n8k16.row.col.f32.f16.f16.f32 "
        "{%0,%1,%2,%3}, {%4,%5,%6,%7}, {%8,%9}, {%0,%1,%2,%3};"
        : "+f"(d[0]), "+f"(d[1]), "+f"(d[2]), "+f"(d[3])
        : "r"(a[0]), "r"(a[1]), "r"(a[2]), "r"(a[3]), "r"(b[0]), "r"(b[1]));
}

// pack {lo, hi} floats into bf16x2 / f16x2 register
__device__ __forceinline__ uint32_t pkbf(float lo, float hi) {
    uint32_t d;
    asm("cvt.rn.bf16x2.f32 %0, %1, %2;" : "=r"(d) : "f"(hi), "f"(lo));
    return d;
}
__device__ __forceinline__ uint32_t pkhf(float lo, float hi) {
    uint32_t d;
    asm("cvt.rn.f16x2.f32 %0, %1, %2;" : "=r"(d) : "f"(hi), "f"(lo));
    return d;
}

// ---------------------------------------------------------------------------
// Scratch (allocation-free: __device__ globals)
// ---------------------------------------------------------------------------
__device__ float g_q[MM*DD];        // reused as bf16 q buffer
__device__ float g_k[MM*DD];        // reused as bf16 k buffer
__device__ float g_v[MM*DD];        // reused as bf16 v buffer
__device__ float g_y[MM*DD];
__device__ float g_x[MM*DD];
__device__ unsigned char g_mask[TT*TT];
__device__ int g_mask_mode;

__device__ __nv_bfloat16 g_srcB[MM*DD];
__device__ __nv_bfloat16 g_attnB[MM*DD];
__device__ __half        g_xF[MM*DD];
__device__ __half        g_hF[MM*FF];
__device__ __nv_bfloat16 g_qwH[DD*DD];
__device__ __nv_bfloat16 g_kwH[DD*DD];
__device__ __nv_bfloat16 g_vwH[DD*DD];
__device__ __nv_bfloat16 g_owH[DD*DD];
__device__ __half        g_l1F[FF*DD];
__device__ __half        g_l2F[DD*FF];

// ---------------------------------------------------------------------------
// fp32 -> bf16 / fp16 converts
// ---------------------------------------------------------------------------
__global__ __launch_bounds__(256)
void tobf16_kernel(const float* __restrict__ x, __nv_bfloat16* __restrict__ out, int n4)
{
    int i = blockIdx.x * 256 + threadIdx.x;
    if (i >= n4) return;
    float4 v = ((const float4*)x)[i];
    ((uint2*)out)[i] = make_uint2(pkbf(v.x, v.y), pkbf(v.z, v.w));
}

__global__ __launch_bounds__(256)
void tofp16_kernel(const float* __restrict__ x, __half* __restrict__ out, int n4)
{
    int i = blockIdx.x * 256 + threadIdx.x;
    if (i >= n4) return;
    float4 v = ((const float4*)x)[i];
    ((uint2*)out)[i] = make_uint2(pkhf(v.x, v.y), pkhf(v.z, v.w));
}

// ---------------------------------------------------------------------------
// Mask dtype detection (prefix scan — statistically conclusive) + convert
// ---------------------------------------------------------------------------
__global__ __launch_bounds__(1024)
void mask_scan_kernel(const uint32_t* __restrict__ m)
{
    const int tid = threadIdx.x;
    int u8f = 0, f32f = 0;
    const int NW = 65536;   // 256KB prefix; buffer is >= 4MB in every mode
    for (int i = tid; i < NW; i += 1024) {
        uint32_t w = m[i];
        if (w != 0u && w != 1u && w != 0x3F800000u) u8f = 1;
        if (w == 0x3F800000u) f32f = 1;
    }
    __shared__ int s_u8, s_f32;
    if (tid == 0) { s_u8 = 0; s_f32 = 0; }
    __syncthreads();
    if (u8f)  atomicOr(&s_u8, 1);
    if (f32f) atomicOr(&s_f32, 1);
    __syncthreads();
    if (tid == 0)
        g_mask_mode = s_u8 ? 0 : (s_f32 ? 2 : 1);
}

__global__ __launch_bounds__(256)
void mask_convert_kernel(const void* __restrict__ min)
{
    const int mode = g_mask_mode;
    int i = blockIdx.x * blockDim.x + threadIdx.x;
    const int NW = (TT*TT) / 4;
    if (i >= NW) return;
    uint32_t out;
    if (mode == 0) {
        out = ((const uint32_t*)min)[i];
    } else if (mode == 1) {
        const int* p = (const int*)min;
        out  = (uint32_t)(p[4*i+0] != 0);
        out |= (uint32_t)(p[4*i+1] != 0) << 8;
        out |= (uint32_t)(p[4*i+2] != 0) << 16;
        out |= (uint32_t)(p[4*i+3] != 0) << 24;
    } else {
        const float* p = (const float*)min;
        out  = (uint32_t)(p[4*i+0] != 0.f);
        out |= (uint32_t)(p[4*i+1] != 0.f) << 8;
        out |= (uint32_t)(p[4*i+2] != 0.f) << 16;
        out |= (uint32_t)(p[4*i+3] != 0.f) << 24;
    }
    ((uint32_t*)g_mask)[i] = out;
}

// ---------------------------------------------------------------------------
// 1-term GEMM via mma.sync (bf16 or fp16 operands, fp32 accumulate)
// acc = A[m,k] * B[n,k]
// EPI: 2 = res + alpha*(acc+bias) -> f32 C
//      3 = bias -> 16-bit out
//      5 = bias+relu -> 16-bit out
// HALF: 0 = bf16 operands/output, 1 = fp16
// 64KB smem (2 stages x 2 tiles) -> 2 CTAs/SM.
// ---------------------------------------------------------------------------
#define TILE_B   16384                 // 128 rows x 128 bytes (64 halves)
#define BSTAGE_B (2*TILE_B)
#define GBF_DYN  (2*BSTAGE_B + 1024)

template<int EPI, int HALF>
__global__ __launch_bounds__(256, 2)
void gemm_bf(const void* __restrict__ Av, const void* __restrict__ Bv,
             const float* __restrict__ bias, float* __restrict__ C,
             int M, int N, int K,
             const float* __restrict__ res, const float* __restrict__ alpha_p,
             void* __restrict__ outv)
{
    const uint16_t* A = (const uint16_t*)Av;
    const uint16_t* B = (const uint16_t*)Bv;
    uint16_t* out = (uint16_t*)outv;

    extern __shared__ unsigned char sm[];
    const uint32_t smu  = smem_u32(sm);
    const uint32_t base = (smu + 1023) & ~1023u;

    const int tid  = threadIdx.x;
    const int wid  = tid >> 5;
    const int lane = tid & 31;
    const int wm   = wid >> 2;
    const int wn   = wid & 3;
    const int bm   = blockIdx.y * 128;
    const int bn   = blockIdx.x * 128;

    float d[4][4][4];
    #pragma unroll
    for (int i = 0; i < 4; i++)
        #pragma unroll
        for (int j = 0; j < 4; j++)
            #pragma unroll
            for (int q = 0; q < 4; q++) d[i][j][q] = 0.f;

    const int srow = tid >> 1;
    const int sc0  = (tid & 1) * 4;
    const uint32_t swrowbase = (uint32_t)srow * 128;
    const int rx = srow & 7;

    const int NC = K >> 6;

    {
        const uint32_t st = base;
        #pragma unroll
        for (int j = 0; j < 4; j++) {
            const int c = sc0 + j;
            const uint32_t sw = swrowbase + ((uint32_t)(c ^ rx) << 4);
            cpa16(st + sw,          A + (size_t)(bm + srow) * K + c * 8);
            cpa16(st + TILE_B + sw, B + (size_t)(bn + srow) * K + c * 8);
        }
        CP_COMMIT();
    }

    for (int ch = 0; ch < NC; ch++) {
        CP_WAIT0();
        __syncthreads();

        if (ch + 1 < NC) {
            const uint32_t st = base + ((ch + 1) & 1) * BSTAGE_B;
            const size_t k0 = (size_t)(ch + 1) * 64;
            #pragma unroll
            for (int j = 0; j < 4; j++) {
                const int c = sc0 + j;
                const uint32_t sw = swrowbase + ((uint32_t)(c ^ rx) << 4);
                cpa16(st + sw,          A + (size_t)(bm + srow) * K + k0 + c * 8);
                cpa16(st + TILE_B + sw, B + (size_t)(bn + srow) * K + k0 + c * 8);
            }
            CP_COMMIT();
        }

        const uint32_t st = base + (ch & 1) * BSTAGE_B;
        const uint32_t aS = st, bS = st + TILE_B;

        const int arow_base = wm * 64 + (lane & 15);
        const int akh = lane >> 4;
        const int brow_base = wn * 32 + (lane & 7) + ((lane >> 4) << 3);
        const int bkh = (lane >> 3) & 1;

        #pragma unroll
        for (int k16 = 0; k16 < 4; k16++) {
            uint32_t a[4][4], b[2][4];
            #pragma unroll
            for (int mt = 0; mt < 4; mt++) {
                const int row = arow_base + mt * 16;
                const uint32_t cb = (uint32_t)(k16 * 32 + akh * 16);
                LDM4(a[mt], aS + (uint32_t)row * 128 + (cb ^ ((uint32_t)(row & 7) << 4)));
            }
            #pragma unroll
            for (int bt = 0; bt < 2; bt++) {
                const int row = brow_base + bt * 16;
                const uint32_t cb = (uint32_t)(k16 * 32 + bkh * 16);
                LDM4(b[bt], bS + (uint32_t)row * 128 + (cb ^ ((uint32_t)(row & 7) << 4)));
            }
            #pragma unroll
            for (int mt = 0; mt < 4; mt++)
                #pragma unroll
                for (int nt = 0; nt < 4; nt++) {
                    if (HALF) mma_fp16(d[mt][nt], a[mt], &b[nt >> 1][(nt & 1) * 2]);
                    else      mma_bf16(d[mt][nt], a[mt], &b[nt >> 1][(nt & 1) * 2]);
                }
        }
        __syncthreads();
    }

    float alpha = 0.f;
    if (EPI == 2) alpha = *alpha_p;
    const int g  = lane >> 2;
    const int nq = (lane & 3) * 2;

    #pragma unroll
    for (int mt = 0; mt < 4; mt++) {
        const int m0 = bm + wm * 64 + mt * 16 + g;
        #pragma unroll
        for (int nt = 0; nt < 4; nt++) {
            const int n = bn + wn * 32 + nt * 8 + nq;
            float2 b2 = *(const float2*)&bias[n];
            float2 o0 = make_float2(d[mt][nt][0] + b2.x, d[mt][nt][1] + b2.y);
            float2 o1 = make_float2(d[mt][nt][2] + b2.x, d[mt][nt][3] + b2.y);
            if (EPI == 5) {
                o0.x = fmaxf(o0.x, 0.f); o0.y = fmaxf(o0.y, 0.f);
                o1.x = fmaxf(o1.x, 0.f); o1.y = fmaxf(o1.y, 0.f);
            }
            if (EPI == 2) {
                float2 r0 = *(const float2*)&res[(size_t)m0 * N + n];
                float2 r1 = *(const float2*)&res[(size_t)(m0 + 8) * N + n];
                o0.x = r0.x + alpha * o0.x; o0.y = r0.y + alpha * o0.y;
                o1.x = r1.x + alpha * o1.x; o1.y = r1.y + alpha * o1.y;
                *(float2*)&C[(size_t)m0 * N + n]       = o0;
                *(float2*)&C[(size_t)(m0 + 8) * N + n] = o1;
            } else {
                uint32_t p0 = HALF ? pkhf(o0.x, o0.y) : pkbf(o0.x, o0.y);
                uint32_t p1 = HALF ? pkhf(o1.x, o1.y) : pkbf(o1.x, o1.y);
                *(uint32_t*)&out[(size_t)m0 * N + n]       = p0;
                *(uint32_t*)&out[(size_t)(m0 + 8) * N + n] = p1;
            }
        }
    }
}

// ---------------------------------------------------------------------------
// Tensor-core flash attention (bf16 mma, fp32 softmax). Plain bf16 output.
// ---------------------------------------------------------------------------
#define MPAD 80
#define KV_B  8192
#define MB_B  (128*MPAD)
#define BUF_B (2*KV_B + MB_B)
#define ATT_SMEM (16384 + 2*BUF_B + 1024)

__global__ __launch_bounds__(256, 2)
void flash_attn_tc(const __nv_bfloat16* __restrict__ Qb, const __nv_bfloat16* __restrict__ Kb,
                   const __nv_bfloat16* __restrict__ Vb, const unsigned char* __restrict__ mask,
                   __nv_bfloat16* __restrict__ OH)
{
    extern __shared__ unsigned char sm[];
    const uint32_t smu = smem_u32(sm);
    const uint32_t Qs  = (smu + 1023) & ~1023u;

    const int tid = threadIdx.x, wid = tid >> 5, lane = tid & 31;
    const int q0 = blockIdx.x * 128;
    const int h  = blockIdx.y, b = blockIdx.z;
    const size_t rowbase = (size_t)b * TT;
    const int colh = h * DHH;

    {
        const int r = tid >> 1, c0 = (tid & 1) * 4;
        const __nv_bfloat16* src = Qb + (rowbase + q0 + r) * DD + colh;
        #pragma unroll
        for (int j = 0; j < 4; j++) {
            const int c = c0 + j;
            cpa16(Qs + r * 128 + ((uint32_t)(c ^ (r & 7)) << 4), src + c * 8);
        }
    }
    {
        const uint32_t Ks = Qs + 16384, Vs = Ks + KV_B, Ms = Vs + KV_B;
        const int r = tid >> 2;
        const int j2 = tid & 3;
        #pragma unroll
        for (int j = 0; j < 2; j++) {
            const int c = j2 * 2 + j;
            const uint32_t sw = r * 128 + ((uint32_t)(c ^ (r & 7)) << 4);
            cpa16(Ks + sw, Kb + (rowbase + r) * DD + colh + c * 8);
            cpa16(Vs + sw, Vb + (rowbase + r) * DD + colh + c * 8);
        }
        const int mr = tid >> 1;
        #pragma unroll
        for (int j = 0; j < 2; j++) {
            const int c = (tid & 1) * 2 + j;
            cpa16(Ms + mr * MPAD + c * 16, mask + (size_t)(q0 + mr) * TT + c * 16);
        }
        CP_COMMIT();
    }

    float m0 = -1e30f, m1 = -1e30f, l0 = 0.f, l1 = 0.f;
    float o[8][4];
    #pragma unroll
    for (int i = 0; i < 8; i++)
        #pragma unroll
        for (int j = 0; j < 4; j++) o[i][j] = 0.f;

    uint32_t aQ[4][4];
    const int arow = wid * 16 + (lane & 15);
    const int akh  = lane >> 4;
    const int brow = (lane & 7) + ((lane >> 4) << 3);
    const int bkh  = (lane >> 3) & 1;
    const int r0   = lane >> 2;
    const int cq   = (lane & 3) * 2;

    const int NT = TT / 64;
    for (int st = 0; st < NT; st++) {
        if (st + 1 < NT) {
            const uint32_t base = Qs + 16384 + ((st + 1) & 1) * BUF_B;
            const uint32_t Ks = base, Vs = base + KV_B, Ms = base + 2*KV_B;
            const int s1 = (st + 1) * 64;
            const int r = tid >> 2, j2 = tid & 3;
            #pragma unroll
            for (int j = 0; j < 2; j++) {
                const int c = j2 * 2 + j;
                const uint32_t sw = r * 128 + ((uint32_t)(c ^ (r & 7)) << 4);
                cpa16(Ks + sw, Kb + (rowbase + s1 + r) * DD + colh + c * 8);
                cpa16(Vs + sw, Vb + (rowbase + s1 + r) * DD + colh + c * 8);
            }
            const int mr = tid >> 1;
            #pragma unroll
            for (int j = 0; j < 2; j++) {
                const int c = (tid & 1) * 2 + j;
                cpa16(Ms + mr * MPAD + c * 16, mask + (size_t)(q0 + mr) * TT + s1 + c * 16);
            }
            CP_COMMIT();
            CP_WAIT1();
        } else {
            CP_WAIT0();
        }
        __syncthreads();

        if (st == 0) {
            #pragma unroll
            for (int kt = 0; kt < 4; kt++) {
                const uint32_t cb = (uint32_t)(kt * 32 + akh * 16);
                LDM4(aQ[kt], Qs + (uint32_t)arow * 128 + (cb ^ ((uint32_t)(arow & 7) << 4)));
            }
        }

        const uint32_t base = Qs + 16384 + (st & 1) * BUF_B;
        const uint32_t Ks = base, Vs = base + KV_B, Ms = base + 2*KV_B;

        float sacc[8][4];
        #pragma unroll
        for (int i = 0; i < 8; i++)
            #pragma unroll
            for (int j = 0; j < 4; j++) sacc[i][j] = 0.f;

        #pragma unroll
        for (int kt = 0; kt < 4; kt++) {
            uint32_t bK[4][4];
            #pragma unroll
            for (int bt = 0; bt < 4; bt++) {
                const int row = brow + bt * 16;
                const uint32_t cb = (uint32_t)(kt * 32 + bkh * 16);
                LDM4(bK[bt], Ks + (uint32_t)row * 128 + (cb ^ ((uint32_t)(row & 7) << 4)));
            }
            #pragma unroll
            for (int nt = 0; nt < 8; nt++)
                mma_bf16(sacc[nt], aQ[kt], &bK[nt >> 1][(nt & 1) * 2]);
        }

        const int mrow0 = wid * 16 + r0;
        float mx0 = -1e30f, mx1 = -1e30f;
        #pragma unroll
        for (int nt = 0; nt < 8; nt++) {
            uchar2 k0 = *(const uchar2*)(sm + (Ms - smu) + mrow0 * MPAD + nt * 8 + cq);
            uchar2 k1 = *(const uchar2*)(sm + (Ms - smu) + (mrow0 + 8) * MPAD + nt * 8 + cq);
            sacc[nt][0] = k0.x ? -1e30f : sacc[nt][0] * 0.125f;
            sacc[nt][1] = k0.y ? -1e30f : sacc[nt][1] * 0.125f;
            sacc[nt][2] = k1.x ? -1e30f : sacc[nt][2] * 0.125f;
            sacc[nt][3] = k1.y ? -1e30f : sacc[nt][3] * 0.125f;
            mx0 = fmaxf(mx0, fmaxf(sacc[nt][0], sacc[nt][1]));
            mx1 = fmaxf(mx1, fmaxf(sacc[nt][2], sacc[nt][3]));
        }
        mx0 = fmaxf(mx0, __shfl_xor_sync(0xffffffffu, mx0, 1));
        mx0 = fmaxf(mx0, __shfl_xor_sync(0xffffffffu, mx0, 2));
        mx1 = fmaxf(mx1, __shfl_xor_sync(0xffffffffu, mx1, 1));
        mx1 = fmaxf(mx1, __shfl_xor_sync(0xffffffffu, mx1, 2));

        const float mn0 = fmaxf(m0, mx0), mn1 = fmaxf(m1, mx1);
        const float af0 = __expf(m0 - mn0), af1 = __expf(m1 - mn1);
        float rs0 = 0.f, rs1 = 0.f;
        #pragma unroll
        for (int nt = 0; nt < 8; nt++) {
            float p0 = (sacc[nt][0] == -1e30f) ? 0.f : __expf(sacc[nt][0] - mn0);
            float p1 = (sacc[nt][1] == -1e30f) ? 0.f : __expf(sacc[nt][1] - mn0);
            float p2 = (sacc[nt][2] == -1e30f) ? 0.f : __expf(sacc[nt][2] - mn1);
            float p3 = (sacc[nt][3] == -1e30f) ? 0.f : __expf(sacc[nt][3] - mn1);
            sacc[nt][0] = p0; sacc[nt][1] = p1; sacc[nt][2] = p2; sacc[nt][3] = p3;
            rs0 += p0 + p1; rs1 += p2 + p3;
        }
        rs0 += __shfl_xor_sync(0xffffffffu, rs0, 1);
        rs0 += __shfl_xor_sync(0xffffffffu, rs0, 2);
        rs1 += __shfl_xor_sync(0xffffffffu, rs1, 1);
        rs1 += __shfl_xor_sync(0xffffffffu, rs1, 2);
        l0 = af0 * l0 + rs0;  m0 = mn0;
        l1 = af1 * l1 + rs1;  m1 = mn1;

        #pragma unroll
        for (int nt = 0; nt < 8; nt++) {
            o[nt][0] *= af0; o[nt][1] *= af0;
            o[nt][2] *= af1; o[nt][3] *= af1;
        }

        uint32_t pf[4][4];
        #pragma unroll
        for (int kt = 0; kt < 4; kt++) {
            pf[kt][0] = pkbf(sacc[2*kt][0],   sacc[2*kt][1]);
            pf[kt][1] = pkbf(sacc[2*kt][2],   sacc[2*kt][3]);
            pf[kt][2] = pkbf(sacc[2*kt+1][0], sacc[2*kt+1][1]);
            pf[kt][3] = pkbf(sacc[2*kt+1][2], sacc[2*kt+1][3]);
        }

        #pragma unroll
        for (int kt = 0; kt < 4; kt++) {
            #pragma unroll
            for (int nt2 = 0; nt2 < 4; nt2++) {
                uint32_t bV[4];
                const int rv = kt * 16 + (lane & 15);
                const uint32_t c = (uint32_t)(nt2 * 2 + (lane >> 4));
                LDM4T(bV, Vs + (uint32_t)rv * 128 + ((c ^ (uint32_t)(rv & 7)) << 4));
                mma_bf16(o[2*nt2],     pf[kt], &bV[0]);
                mma_bf16(o[2*nt2 + 1], pf[kt], &bV[2]);
            }
        }
        __syncthreads();
    }

    const float inv0 = (l0 > 0.f) ? 1.f / l0 : 0.f;
    const float inv1 = (l1 > 0.f) ? 1.f / l1 : 0.f;
    const size_t row0 = rowbase + q0 + wid * 16 + r0;
    #pragma unroll
    for (int nt = 0; nt < 8; nt++) {
        const int n = colh + nt * 8 + cq;
        *(uint32_t*)&OH[row0 * DD + n]       = pkbf(o[nt][0] * inv0, o[nt][1] * inv0);
        *(uint32_t*)&OH[(row0 + 8) * DD + n] = pkbf(o[nt][2] * inv1, o[nt][3] * inv1);
    }
}

// ---------------------------------------------------------------------------
// Row LayerNorm; F16OUT=1 additionally emits fp16 copy of the output.
// ---------------------------------------------------------------------------
template<int F16OUT>
__global__ __launch_bounds__(256)
void ln_kernel(const float* __restrict__ Y, const float* __restrict__ sc,
               const float* __restrict__ bi, float* __restrict__ X,
               __half* __restrict__ outF)
{
    const int row = blockIdx.x;
    const int tid = threadIdx.x;
    const float4 v = ((const float4*)(Y + (size_t)row * DD))[tid];

    float s  = v.x + v.y + v.z + v.w;
    float ss = v.x*v.x + v.y*v.y + v.z*v.z + v.w*v.w;
    #pragma unroll
    for (int off = 16; off >= 1; off >>= 1) {
        s  += __shfl_xor_sync(0xffffffffu, s,  off);
        ss += __shfl_xor_sync(0xffffffffu, ss, off);
    }

    __shared__ float ws[8], wss[8];
    __shared__ float mean_sh, rstd_sh;
    if ((tid & 31) == 0) { ws[tid >> 5] = s; wss[tid >> 5] = ss; }
    __syncthreads();
    if (tid == 0) {
        float S = 0.f, SS = 0.f;
        #pragma unroll
        for (int k = 0; k < 8; k++) { S += ws[k]; SS += wss[k]; }
        float mu = S / (float)DD;
        float var = SS / (float)DD - mu * mu;
        mean_sh = mu;
        rstd_sh = rsqrtf(var + 1e-5f);
    }
    __syncthreads();
    const float mu = mean_sh, rs = rstd_sh;

    const float4 sc4 = ((const float4*)sc)[tid];
    const float4 b4  = ((const float4*)bi)[tid];
    float4 o;
    o.x = (v.x - mu) * rs * sc4.x + b4.x;
    o.y = (v.y - mu) * rs * sc4.y + b4.y;
    o.z = (v.z - mu) * rs * sc4.z + b4.z;
    o.w = (v.w - mu) * rs * sc4.w + b4.w;
    ((float4*)(X + (size_t)row * DD))[tid] = o;

    if (F16OUT) {
        uint2 fv = make_uint2(pkhf(o.x, o.y), pkhf(o.z, o.w));
        *(uint2*)&outF[(size_t)row * DD + tid * 4] = fv;
    }
}

// ---------------------------------------------------------------------------
// Launch
// ---------------------------------------------------------------------------
extern "C" void kernel_launch(void* const* d_in, const int* in_sizes, int n_in,
                              void* d_out, int out_size)
{
    const float* src  = (const float*)d_in[0];
    const void*  mask_raw = d_in[1];
    const float* q_w = (const float*)d_in[2];
    const float* q_b = (const float*)d_in[3];
    const float* k_w = (const float*)d_in[4];
    const float* k_b = (const float*)d_in[5];
    const float* v_w = (const float*)d_in[6];
    const float* v_b = (const float*)d_in[7];
    const float* o_w = (const float*)d_in[8];
    const float* o_b = (const float*)d_in[9];
    const float* l1_w = (const float*)d_in[10];
    const float* l1_b = (const float*)d_in[11];
    const float* l2_w = (const float*)d_in[12];
    const float* l2_b = (const float*)d_in[13];
    const float* n1_s = (const float*)d_in[14];
    const float* n1_b = (const float*)d_in[15];
    const float* n2_s = (const float*)d_in[16];
    const float* n2_b = (const float*)d_in[17];
    const float* alpha_attn = (const float*)d_in[18];
    const float* alpha_ff   = (const float*)d_in[19];

    float *y, *x;
    unsigned char* maskc;
    __nv_bfloat16 *qB, *kB, *vB, *srcB, *attnB;
    __nv_bfloat16 *qwH, *kwH, *vwH, *owH;
    __half *xF, *hF, *l1F, *l2F;
    cudaGetSymbolAddress((void**)&qB,   g_q);
    cudaGetSymbolAddress((void**)&kB,   g_k);
    cudaGetSymbolAddress((void**)&vB,   g_v);
    cudaGetSymbolAddress((void**)&y,    g_y);
    cudaGetSymbolAddress((void**)&x,    g_x);
    cudaGetSymbolAddress((void**)&maskc, g_mask);
    cudaGetSymbolAddress((void**)&srcB, g_srcB);
    cudaGetSymbolAddress((void**)&attnB, g_attnB);
    cudaGetSymbolAddress((void**)&xF,   g_xF);
    cudaGetSymbolAddress((void**)&hF,   g_hF);
    cudaGetSymbolAddress((void**)&qwH,  g_qwH);
    cudaGetSymbolAddress((void**)&kwH,  g_kwH);
    cudaGetSymbolAddress((void**)&vwH,  g_vwH);
    cudaGetSymbolAddress((void**)&owH,  g_owH);
    cudaGetSymbolAddress((void**)&l1F,  g_l1F);
    cudaGetSymbolAddress((void**)&l2F,  g_l2F);

    cudaFuncSetAttribute((const void*)gemm_bf<2,0>, cudaFuncAttributeMaxDynamicSharedMemorySize, GBF_DYN);
    cudaFuncSetAttribute((const void*)gemm_bf<3,0>, cudaFuncAttributeMaxDynamicSharedMemorySize, GBF_DYN);
    cudaFuncSetAttribute((const void*)gemm_bf<2,1>, cudaFuncAttributeMaxDynamicSharedMemorySize, GBF_DYN);
    cudaFuncSetAttribute((const void*)gemm_bf<5,1>, cudaFuncAttributeMaxDynamicSharedMemorySize, GBF_DYN);
    cudaFuncSetAttribute(flash_attn_tc, cudaFuncAttributeMaxDynamicSharedMemorySize, ATT_SMEM);

    dim3 blk(256);
    dim3 grid_qkv(DD/128, MM/128);    // (8, 32)
    dim3 grid_ff1(FF/128, MM/128);    // (32, 32)

    // Mask canonicalization
    mask_scan_kernel<<<1, 1024>>>((const uint32_t*)mask_raw);
    mask_convert_kernel<<<(TT*TT/4 + 255)/256, 256>>>(mask_raw);

    // Weight conversions
    tobf16_kernel<<<(DD*DD/4 + 255)/256, 256>>>(q_w, qwH, DD*DD/4);
    tobf16_kernel<<<(DD*DD/4 + 255)/256, 256>>>(k_w, kwH, DD*DD/4);
    tobf16_kernel<<<(DD*DD/4 + 255)/256, 256>>>(v_w, vwH, DD*DD/4);
    tobf16_kernel<<<(DD*DD/4 + 255)/256, 256>>>(o_w, owH, DD*DD/4);
    tofp16_kernel<<<(FF*DD/4 + 255)/256, 256>>>(l1_w, l1F, FF*DD/4);
    tofp16_kernel<<<(DD*FF/4 + 255)/256, 256>>>(l2_w, l2F, DD*FF/4);
    tobf16_kernel<<<(MM*DD/4 + 255)/256, 256>>>(src, srcB, MM*DD/4);

    // QKV projections (1-term bf16) -> bf16 q/k/v
    gemm_bf<3,0><<<grid_qkv, blk, GBF_DYN>>>(srcB, qwH, q_b, nullptr, MM, DD, DD, nullptr, nullptr, qB);
    gemm_bf<3,0><<<grid_qkv, blk, GBF_DYN>>>(srcB, kwH, k_b, nullptr, MM, DD, DD, nullptr, nullptr, kB);
    gemm_bf<3,0><<<grid_qkv, blk, GBF_DYN>>>(srcB, vwH, v_b, nullptr, MM, DD, DD, nullptr, nullptr, vB);

    // Flash attention -> plain bf16
    flash_attn_tc<<<dim3(TT/128, HH, BB), blk, ATT_SMEM>>>(qB, kB, vB, maskc, attnB);

    // O projection (1-term bf16) + residual, LN1 (emits fp16 x)
    gemm_bf<2,0><<<grid_qkv, blk, GBF_DYN>>>(attnB, owH, o_b, y, MM, DD, DD, src, alpha_attn, nullptr);
    ln_kernel<1><<<MM, 256>>>(y, n1_s, n1_b, x, xF);

    // FFN (1-term fp16)
    gemm_bf<5,1><<<grid_ff1, blk, GBF_DYN>>>(xF, l1F, l1_b, nullptr, MM, FF, DD, nullptr, nullptr, hF);
    gemm_bf<2,1><<<grid_qkv, blk, GBF_DYN>>>(hF, l2F, l2_b, y, MM, DD, FF, x, alpha_ff, nullptr);
    ln_kernel<0><<<MM, 256>>>(y, n2_s, n2_b, (float*)d_out, nullptr);
}